// round 1
// baseline (speedup 1.0000x reference)
#include <cuda_runtime.h>
#include <math.h>

#define B_  2
#define S_  2048
#define D_  1024
#define H_  16
#define DH_ 64
#define MTOT (B_*S_)   // 4096

// Scratch: projected Q, K, V and attention context (each 16 MB)
__device__ float g_Q[MTOT*D_];
__device__ float g_K[MTOT*D_];
__device__ float g_V[MTOT*D_];
__device__ float g_C[MTOT*D_];

// ---------------------------------------------------------------------------
// GEMM: Y[M,1024] = X[M,1024] @ W[1024,1024]^T + bias   (M = 4096)
// 64x64 block tile, BK=32, 256 threads, 4x4 micro-tile.
// Both tiles stored K-transposed in smem (stride 68) so the compute loop
// does conflict-free float4 reads.
// ---------------------------------------------------------------------------
__global__ __launch_bounds__(256) void gemm_bias_kernel(
    const float* __restrict__ X, const float* __restrict__ W,
    const float* __restrict__ bias, float* __restrict__ Y)
{
    __shared__ float sX[32][68];
    __shared__ float sW[32][68];
    const int tid = threadIdx.x;
    const int tx = tid & 15, ty = tid >> 4;
    const int m0 = blockIdx.y * 64, n0 = blockIdx.x * 64;
    const int lr = tid >> 3;          // 0..31
    const int lk = (tid & 7) << 2;    // 0,4,...,28

    float acc[4][4];
    #pragma unroll
    for (int i = 0; i < 4; i++)
        #pragma unroll
        for (int j = 0; j < 4; j++) acc[i][j] = 0.f;

    for (int k0 = 0; k0 < D_; k0 += 32) {
        #pragma unroll
        for (int w = 0; w < 2; w++) {
            int row = lr + 32*w;
            float4 xv = *(const float4*)&X[(size_t)(m0+row)*D_ + k0 + lk];
            sX[lk+0][row]=xv.x; sX[lk+1][row]=xv.y; sX[lk+2][row]=xv.z; sX[lk+3][row]=xv.w;
            float4 wv = *(const float4*)&W[(size_t)(n0+row)*D_ + k0 + lk];
            sW[lk+0][row]=wv.x; sW[lk+1][row]=wv.y; sW[lk+2][row]=wv.z; sW[lk+3][row]=wv.w;
        }
        __syncthreads();
        #pragma unroll 8
        for (int kk = 0; kk < 32; kk++) {
            float4 a = *(const float4*)&sX[kk][ty<<2];
            float4 b = *(const float4*)&sW[kk][tx<<2];
            float av[4] = {a.x, a.y, a.z, a.w};
            float bv[4] = {b.x, b.y, b.z, b.w};
            #pragma unroll
            for (int i = 0; i < 4; i++)
                #pragma unroll
                for (int j = 0; j < 4; j++)
                    acc[i][j] = fmaf(av[i], bv[j], acc[i][j]);
        }
        __syncthreads();
    }

    #pragma unroll
    for (int i = 0; i < 4; i++) {
        int row = m0 + (ty<<2) + i;
        int col = n0 + (tx<<2);
        float4 o;
        o.x = acc[i][0] + bias[col+0];
        o.y = acc[i][1] + bias[col+1];
        o.z = acc[i][2] + bias[col+2];
        o.w = acc[i][3] + bias[col+3];
        *(float4*)&Y[(size_t)row*D_ + col] = o;
    }
}

// ---------------------------------------------------------------------------
// RoPE (reference variant), in-place on g_Q and g_K.
// One thread per (b, s, h, pair).
// out_even = x1*sin - x2*cos ; out_odd = -x1*cos - x2*sin
// inv = exp(arange(0,64,2) * (-(4*log(10))/64)) computed in fp32-matching way.
// ---------------------------------------------------------------------------
__global__ __launch_bounds__(256) void rope_kernel()
{
    __shared__ float sinv[32];
    if (threadIdx.x < 32) {
        float coef = -(4.0f * logf(10.0f)) / 64.0f;             // fp32, matches ref
        float arg  = (float)(2 * threadIdx.x) * coef;           // fp32 product
        sinv[threadIdx.x] = (float)exp((double)arg);            // correctly-rounded fp32 exp
    }
    __syncthreads();

    int idx = blockIdx.x * blockDim.x + threadIdx.x;  // over B*S*H*32
    int j = idx & 31;
    int t = idx >> 5;
    int h = t & (H_ - 1);
    int rowi = t >> 4;                 // b*S + s
    int s = rowi & (S_ - 1);

    float ang = (float)s * sinv[j];
    float sn, cs;
    sincosf(ang, &sn, &cs);            // accurate range reduction

    size_t base = (size_t)rowi * D_ + h * DH_ + 2 * j;
    float x1 = g_Q[base], x2 = g_Q[base+1];
    g_Q[base]   =  x1 * sn - x2 * cs;
    g_Q[base+1] = -x1 * cs - x2 * sn;
    x1 = g_K[base]; x2 = g_K[base+1];
    g_K[base]   =  x1 * sn - x2 * cs;
    g_K[base+1] = -x1 * cs - x2 * sn;
}

// ---------------------------------------------------------------------------
// Causal flash attention, fp32, online softmax. No score scaling (ref has none).
// Grid: (32 q-blocks, 32 b*h). Block: 256 threads. Tiles 64x64.
// smem: Qt[64][68] (d-major), K/P alias [64][68], V[64][64].
// ---------------------------------------------------------------------------
__global__ __launch_bounds__(256) void attn_kernel()
{
    extern __shared__ float sm[];
    float* sQt = sm;                 // [d][m] stride 68
    float* sKP = sm + 64*68;         // K transposed [d][c] -> later P transposed [c][r]
    float* sV  = sm + 2*64*68;       // [c][d] stride 64

    const int qb = gridDim.x - 1 - blockIdx.x;   // long blocks first
    const int bh = blockIdx.y;
    const int b = bh >> 4, h = bh & 15;
    const int tid = threadIdx.x, tx = tid & 15, ty = tid >> 4;
    const size_t headoff = (size_t)b * S_ * D_ + (size_t)h * DH_;
    const float* Qg = g_Q + headoff;
    const float* Kg = g_K + headoff;
    const float* Vg = g_V + headoff;

    const int lr = tid >> 4;            // 0..15
    const int ld = (tid & 15) << 2;     // 0..60

    // Load Q tile (transposed into sQt)
    #pragma unroll
    for (int w = 0; w < 4; w++) {
        int m = lr + 16*w;
        float4 qv = *(const float4*)&Qg[(size_t)(qb*64+m)*D_ + ld];
        sQt[(ld+0)*68+m]=qv.x; sQt[(ld+1)*68+m]=qv.y;
        sQt[(ld+2)*68+m]=qv.z; sQt[(ld+3)*68+m]=qv.w;
    }

    float m_r[4], l_r[4], o[4][4];
    #pragma unroll
    for (int i = 0; i < 4; i++) {
        m_r[i] = -1e30f; l_r[i] = 0.f;
        #pragma unroll
        for (int j = 0; j < 4; j++) o[i][j] = 0.f;
    }

    for (int kb = 0; kb <= qb; kb++) {
        // Load K (transposed) and V (natural)
        #pragma unroll
        for (int w = 0; w < 4; w++) {
            int c = lr + 16*w;
            float4 kv = *(const float4*)&Kg[(size_t)(kb*64+c)*D_ + ld];
            sKP[(ld+0)*68+c]=kv.x; sKP[(ld+1)*68+c]=kv.y;
            sKP[(ld+2)*68+c]=kv.z; sKP[(ld+3)*68+c]=kv.w;
            float4 vv = *(const float4*)&Vg[(size_t)(kb*64+c)*D_ + ld];
            *(float4*)&sV[c*64+ld] = vv;
        }
        __syncthreads();

        // S = Q K^T (64x64x64)
        float s_[4][4];
        #pragma unroll
        for (int i = 0; i < 4; i++)
            #pragma unroll
            for (int j = 0; j < 4; j++) s_[i][j] = 0.f;
        #pragma unroll 8
        for (int d = 0; d < 64; d++) {
            float4 a  = *(const float4*)&sQt[d*68 + (ty<<2)];
            float4 bb = *(const float4*)&sKP[d*68 + (tx<<2)];
            float av[4] = {a.x, a.y, a.z, a.w};
            float bv[4] = {bb.x, bb.y, bb.z, bb.w};
            #pragma unroll
            for (int i = 0; i < 4; i++)
                #pragma unroll
                for (int j = 0; j < 4; j++)
                    s_[i][j] = fmaf(av[i], bv[j], s_[i][j]);
        }
        __syncthreads();   // all GEMM1 reads of sKP done -> safe to alias with P

        // Causal mask on the diagonal tile
        if (kb == qb) {
            #pragma unroll
            for (int i = 0; i < 4; i++)
                #pragma unroll
                for (int j = 0; j < 4; j++)
                    if (((tx<<2)+j) > ((ty<<2)+i)) s_[i][j] = -1e30f;
        }

        // Online softmax per row; write P (transposed) into sKP
        #pragma unroll
        for (int i = 0; i < 4; i++) {
            float mx = fmaxf(fmaxf(s_[i][0], s_[i][1]), fmaxf(s_[i][2], s_[i][3]));
            #pragma unroll
            for (int off = 8; off >= 1; off >>= 1)
                mx = fmaxf(mx, __shfl_xor_sync(0xffffffffu, mx, off));
            float mn = fmaxf(m_r[i], mx);
            float alpha = __expf(m_r[i] - mn);
            float ps = 0.f;
            #pragma unroll
            for (int j = 0; j < 4; j++) {
                float p = __expf(s_[i][j] - mn);
                s_[i][j] = p; ps += p;
            }
            #pragma unroll
            for (int off = 8; off >= 1; off >>= 1)
                ps += __shfl_xor_sync(0xffffffffu, ps, off);
            l_r[i] = l_r[i]*alpha + ps;
            m_r[i] = mn;
            #pragma unroll
            for (int j = 0; j < 4; j++) {
                o[i][j] *= alpha;
                sKP[((tx<<2)+j)*68 + (ty<<2)+i] = s_[i][j];
            }
        }
        __syncthreads();

        // O += P V (64x64x64)
        #pragma unroll 8
        for (int c = 0; c < 64; c++) {
            float4 a  = *(const float4*)&sKP[c*68 + (ty<<2)];
            float4 vv = *(const float4*)&sV[c*64 + (tx<<2)];
            float av[4] = {a.x, a.y, a.z, a.w};
            float bv[4] = {vv.x, vv.y, vv.z, vv.w};
            #pragma unroll
            for (int i = 0; i < 4; i++)
                #pragma unroll
                for (int j = 0; j < 4; j++)
                    o[i][j] = fmaf(av[i], bv[j], o[i][j]);
        }
        __syncthreads();
    }

    // Epilogue: normalize and write context in [b, s, h*DH + d] layout
    #pragma unroll
    for (int i = 0; i < 4; i++) {
        float invl = 1.0f / l_r[i];
        int srow = qb*64 + (ty<<2) + i;
        float4 ov;
        ov.x = o[i][0]*invl; ov.y = o[i][1]*invl;
        ov.z = o[i][2]*invl; ov.w = o[i][3]*invl;
        *(float4*)&g_C[(size_t)b*S_*D_ + (size_t)srow*D_ + h*DH_ + (tx<<2)] = ov;
    }
}

// ---------------------------------------------------------------------------
extern "C" void kernel_launch(void* const* d_in, const int* in_sizes, int n_in,
                              void* d_out, int out_size)
{
    const float* q  = (const float*)d_in[0];
    const float* k  = (const float*)d_in[1];
    const float* v  = (const float*)d_in[2];
    const float* Wq = (const float*)d_in[3];
    const float* bq = (const float*)d_in[4];
    const float* Wk = (const float*)d_in[5];
    const float* bk = (const float*)d_in[6];
    const float* Wv = (const float*)d_in[7];
    const float* bv = (const float*)d_in[8];
    const float* Wo = (const float*)d_in[9];
    const float* bo = (const float*)d_in[10];
    float* out = (float*)d_out;

    float *Qp, *Kp, *Vp, *Cp;
    cudaGetSymbolAddress((void**)&Qp, g_Q);
    cudaGetSymbolAddress((void**)&Kp, g_K);
    cudaGetSymbolAddress((void**)&Vp, g_V);
    cudaGetSymbolAddress((void**)&Cp, g_C);

    dim3 gg(D_/64, MTOT/64), bb(256);
    gemm_bias_kernel<<<gg, bb>>>(q, Wq, bq, Qp);
    gemm_bias_kernel<<<gg, bb>>>(k, Wk, bk, Kp);
    gemm_bias_kernel<<<gg, bb>>>(v, Wv, bv, Vp);

    rope_kernel<<<(B_*S_*H_*32)/256, 256>>>();

    int smem = (2*64*68 + 64*64) * (int)sizeof(float);  // 51200 B
    cudaFuncSetAttribute(attn_kernel, cudaFuncAttributeMaxDynamicSharedMemorySize, smem);
    attn_kernel<<<dim3(S_/64, B_*H_), 256, smem>>>();

    gemm_bias_kernel<<<gg, bb>>>(Cp, Wo, bo, out);
}

// round 2
// speedup vs baseline: 1.2297x; 1.2297x over previous
#include <cuda_runtime.h>
#include <math.h>

#define B_  2
#define S_  2048
#define D_  1024
#define H_  16
#define DH_ 64
#define MTOT (B_*S_)   // 4096

__device__ float g_Q[MTOT*D_];
__device__ float g_K[MTOT*D_];
__device__ float g_V[MTOT*D_];
__device__ float g_C[MTOT*D_];

// ---------------------------------------------------------------------------
// GEMM: Y[M,1024] = X[M,1024] @ W[1024,1024]^T + bias
// 128x128 tile, BK=16, 256 threads, 8x8 micro-tile, double-buffered smem.
// ---------------------------------------------------------------------------
__global__ __launch_bounds__(256, 2) void gemm_bias_kernel(
    const float* __restrict__ X, const float* __restrict__ W,
    const float* __restrict__ bias, float* __restrict__ Y)
{
    __shared__ float sA[2][16][132];
    __shared__ float sB[2][16][132];
    const int tid = threadIdx.x;
    const int tx = tid & 15, ty = tid >> 4;
    const int m0 = blockIdx.y * 128, n0 = blockIdx.x * 128;
    const int lr = tid >> 2;          // 0..63
    const int lk = (tid & 3) << 2;    // 0,4,8,12

    const float* Xa = X + (size_t)(m0 + lr)      * D_ + lk;
    const float* Xb = X + (size_t)(m0 + lr + 64) * D_ + lk;
    const float* Wa = W + (size_t)(n0 + lr)      * D_ + lk;
    const float* Wb = W + (size_t)(n0 + lr + 64) * D_ + lk;

    float acc[8][8];
    #pragma unroll
    for (int i = 0; i < 8; i++)
        #pragma unroll
        for (int j = 0; j < 8; j++) acc[i][j] = 0.f;

    // preload tile 0
    {
        float4 a0 = *(const float4*)Xa, a1 = *(const float4*)Xb;
        float4 b0 = *(const float4*)Wa, b1 = *(const float4*)Wb;
        sA[0][lk+0][lr]=a0.x; sA[0][lk+1][lr]=a0.y; sA[0][lk+2][lr]=a0.z; sA[0][lk+3][lr]=a0.w;
        sA[0][lk+0][lr+64]=a1.x; sA[0][lk+1][lr+64]=a1.y; sA[0][lk+2][lr+64]=a1.z; sA[0][lk+3][lr+64]=a1.w;
        sB[0][lk+0][lr]=b0.x; sB[0][lk+1][lr]=b0.y; sB[0][lk+2][lr]=b0.z; sB[0][lk+3][lr]=b0.w;
        sB[0][lk+0][lr+64]=b1.x; sB[0][lk+1][lr+64]=b1.y; sB[0][lk+2][lr+64]=b1.z; sB[0][lk+3][lr+64]=b1.w;
    }
    __syncthreads();

    int buf = 0;
    #pragma unroll 1
    for (int k0 = 0; k0 < D_; k0 += 16) {
        float4 pa0, pa1, pb0, pb1;
        const bool more = (k0 + 16 < D_);
        if (more) {
            pa0 = *(const float4*)(Xa + k0 + 16);
            pa1 = *(const float4*)(Xb + k0 + 16);
            pb0 = *(const float4*)(Wa + k0 + 16);
            pb1 = *(const float4*)(Wb + k0 + 16);
        }
        #pragma unroll
        for (int kk = 0; kk < 16; kk++) {
            float4 xa  = *(const float4*)&sA[buf][kk][ty<<2];
            float4 xa2 = *(const float4*)&sA[buf][kk][(ty<<2)+64];
            float4 wb  = *(const float4*)&sB[buf][kk][tx<<2];
            float4 wb2 = *(const float4*)&sB[buf][kk][(tx<<2)+64];
            float av[8] = {xa.x,xa.y,xa.z,xa.w, xa2.x,xa2.y,xa2.z,xa2.w};
            float bv[8] = {wb.x,wb.y,wb.z,wb.w, wb2.x,wb2.y,wb2.z,wb2.w};
            #pragma unroll
            for (int i = 0; i < 8; i++)
                #pragma unroll
                for (int j = 0; j < 8; j++)
                    acc[i][j] = fmaf(av[i], bv[j], acc[i][j]);
        }
        if (more) {
            int nb = buf ^ 1;
            sA[nb][lk+0][lr]=pa0.x; sA[nb][lk+1][lr]=pa0.y; sA[nb][lk+2][lr]=pa0.z; sA[nb][lk+3][lr]=pa0.w;
            sA[nb][lk+0][lr+64]=pa1.x; sA[nb][lk+1][lr+64]=pa1.y; sA[nb][lk+2][lr+64]=pa1.z; sA[nb][lk+3][lr+64]=pa1.w;
            sB[nb][lk+0][lr]=pb0.x; sB[nb][lk+1][lr]=pb0.y; sB[nb][lk+2][lr]=pb0.z; sB[nb][lk+3][lr]=pb0.w;
            sB[nb][lk+0][lr+64]=pb1.x; sB[nb][lk+1][lr+64]=pb1.y; sB[nb][lk+2][lr+64]=pb1.z; sB[nb][lk+3][lr+64]=pb1.w;
            __syncthreads();
            buf = nb;
        }
    }

    #pragma unroll
    for (int i = 0; i < 8; i++) {
        int row = m0 + (ty<<2) + (i & 3) + ((i >> 2) << 6);
        int c0  = n0 + (tx<<2);
        float4 o;
        o.x = acc[i][0] + bias[c0+0];
        o.y = acc[i][1] + bias[c0+1];
        o.z = acc[i][2] + bias[c0+2];
        o.w = acc[i][3] + bias[c0+3];
        *(float4*)&Y[(size_t)row*D_ + c0] = o;
        float4 o2;
        o2.x = acc[i][4] + bias[c0+64];
        o2.y = acc[i][5] + bias[c0+65];
        o2.z = acc[i][6] + bias[c0+66];
        o2.w = acc[i][7] + bias[c0+67];
        *(float4*)&Y[(size_t)row*D_ + c0 + 64] = o2;
    }
}

// ---------------------------------------------------------------------------
// RoPE (reference variant), in-place on g_Q and g_K.
// ---------------------------------------------------------------------------
__global__ __launch_bounds__(256) void rope_kernel()
{
    __shared__ float sinv[32];
    if (threadIdx.x < 32) {
        float coef = -(4.0f * logf(10.0f)) / 64.0f;
        float arg  = (float)(2 * threadIdx.x) * coef;
        sinv[threadIdx.x] = (float)exp((double)arg);
    }
    __syncthreads();

    int idx = blockIdx.x * blockDim.x + threadIdx.x;
    int j = idx & 31;
    int t = idx >> 5;
    int h = t & (H_ - 1);
    int rowi = t >> 4;
    int s = rowi & (S_ - 1);

    float ang = (float)s * sinv[j];
    float sn, cs;
    sincosf(ang, &sn, &cs);

    size_t base = (size_t)rowi * D_ + h * DH_ + 2 * j;
    float x1 = g_Q[base], x2 = g_Q[base+1];
    g_Q[base]   =  x1 * sn - x2 * cs;
    g_Q[base+1] = -x1 * cs - x2 * sn;
    x1 = g_K[base]; x2 = g_K[base+1];
    g_K[base]   =  x1 * sn - x2 * cs;
    g_K[base+1] = -x1 * cs - x2 * sn;
}

// ---------------------------------------------------------------------------
// Causal flash attention. Q tile 128, K tile 64, 256 threads, 8x4 micro-tile.
// smem: sQt [d=64][m=128] stride 132 ; sKP (K^T [d][c] / P^T [c][r]) 64x132 ;
//       sV [c=64][d=64] stride 64.
// ---------------------------------------------------------------------------
__global__ __launch_bounds__(256, 2) void attn_kernel()
{
    extern __shared__ float sm[];
    float* sQt = sm;                 // 64*132
    float* sKP = sm + 64*132;        // 64*132
    float* sV  = sm + 2*64*132;      // 64*64

    const int qb = gridDim.x - 1 - blockIdx.x;   // long blocks first
    const int bh = blockIdx.y;
    const int b = bh >> 4, h = bh & 15;
    const int tid = threadIdx.x, tx = tid & 15, ty = tid >> 4;
    const size_t headoff = (size_t)b * S_ * D_ + (size_t)h * DH_;
    const float* Qg = g_Q + headoff;
    const float* Kg = g_K + headoff;
    const float* Vg = g_V + headoff;

    const int lr = tid >> 4;            // 0..15
    const int ld = (tid & 15) << 2;     // 0..60

    // Load Q tile (128 rows, transposed into sQt)
    #pragma unroll
    for (int w = 0; w < 8; w++) {
        int m = lr + 16*w;
        float4 qv = *(const float4*)&Qg[(size_t)(qb*128+m)*D_ + ld];
        sQt[(ld+0)*132+m]=qv.x; sQt[(ld+1)*132+m]=qv.y;
        sQt[(ld+2)*132+m]=qv.z; sQt[(ld+3)*132+m]=qv.w;
    }

    float m_r[8], l_r[8], o[8][4];
    #pragma unroll
    for (int i = 0; i < 8; i++) {
        m_r[i] = -1e30f; l_r[i] = 0.f;
        #pragma unroll
        for (int j = 0; j < 4; j++) o[i][j] = 0.f;
    }

    const int nkb = 2*qb + 2;   // number of 64-wide k tiles
    for (int kb = 0; kb < nkb; kb++) {
        // Load K (transposed) and V
        #pragma unroll
        for (int w = 0; w < 4; w++) {
            int c = lr + 16*w;
            float4 kv = *(const float4*)&Kg[(size_t)(kb*64+c)*D_ + ld];
            sKP[(ld+0)*132+c]=kv.x; sKP[(ld+1)*132+c]=kv.y;
            sKP[(ld+2)*132+c]=kv.z; sKP[(ld+3)*132+c]=kv.w;
            float4 vv = *(const float4*)&Vg[(size_t)(kb*64+c)*D_ + ld];
            *(float4*)&sV[c*64+ld] = vv;
        }
        __syncthreads();

        // S = Q K^T (128x64x64)
        float s_[8][4];
        #pragma unroll
        for (int i = 0; i < 8; i++)
            #pragma unroll
            for (int j = 0; j < 4; j++) s_[i][j] = 0.f;
        #pragma unroll 4
        for (int d = 0; d < 64; d++) {
            float4 a  = *(const float4*)&sQt[d*132 + (ty<<2)];
            float4 a2 = *(const float4*)&sQt[d*132 + (ty<<2) + 64];
            float4 bb = *(const float4*)&sKP[d*132 + (tx<<2)];
            float av[8] = {a.x,a.y,a.z,a.w, a2.x,a2.y,a2.z,a2.w};
            float bv[4] = {bb.x,bb.y,bb.z,bb.w};
            #pragma unroll
            for (int i = 0; i < 8; i++)
                #pragma unroll
                for (int j = 0; j < 4; j++)
                    s_[i][j] = fmaf(av[i], bv[j], s_[i][j]);
        }
        __syncthreads();   // GEMM1 reads of sKP done -> safe to alias with P

        // Causal mask (diagonal spans the last two k-tiles)
        if (kb >= 2*qb) {
            #pragma unroll
            for (int i = 0; i < 8; i++) {
                int rg = qb*128 + (ty<<2) + (i & 3) + ((i >> 2) << 6);
                #pragma unroll
                for (int j = 0; j < 4; j++) {
                    int cg = kb*64 + (tx<<2) + j;
                    if (cg > rg) s_[i][j] = -1e30f;
                }
            }
        }

        // Online softmax per row; write P (transposed) into sKP
        #pragma unroll
        for (int i = 0; i < 8; i++) {
            float mx = fmaxf(fmaxf(s_[i][0], s_[i][1]), fmaxf(s_[i][2], s_[i][3]));
            #pragma unroll
            for (int off = 8; off >= 1; off >>= 1)
                mx = fmaxf(mx, __shfl_xor_sync(0xffffffffu, mx, off));
            float mn = fmaxf(m_r[i], mx);
            float alpha = __expf(m_r[i] - mn);
            float ps = 0.f;
            #pragma unroll
            for (int j = 0; j < 4; j++) {
                float p = __expf(s_[i][j] - mn);
                s_[i][j] = p; ps += p;
            }
            #pragma unroll
            for (int off = 8; off >= 1; off >>= 1)
                ps += __shfl_xor_sync(0xffffffffu, ps, off);
            l_r[i] = l_r[i]*alpha + ps;
            m_r[i] = mn;
            int row = (ty<<2) + (i & 3) + ((i >> 2) << 6);
            #pragma unroll
            for (int j = 0; j < 4; j++) {
                o[i][j] *= alpha;
                sKP[((tx<<2)+j)*132 + row] = s_[i][j];
            }
        }
        __syncthreads();

        // O += P V (128x64x64)
        #pragma unroll 4
        for (int c = 0; c < 64; c++) {
            float4 a  = *(const float4*)&sKP[c*132 + (ty<<2)];
            float4 a2 = *(const float4*)&sKP[c*132 + (ty<<2) + 64];
            float4 vv = *(const float4*)&sV[c*64 + (tx<<2)];
            float av[8] = {a.x,a.y,a.z,a.w, a2.x,a2.y,a2.z,a2.w};
            float bv[4] = {vv.x,vv.y,vv.z,vv.w};
            #pragma unroll
            for (int i = 0; i < 8; i++)
                #pragma unroll
                for (int j = 0; j < 4; j++)
                    o[i][j] = fmaf(av[i], bv[j], o[i][j]);
        }
        __syncthreads();
    }

    // Epilogue
    #pragma unroll
    for (int i = 0; i < 8; i++) {
        float invl = 1.0f / l_r[i];
        int srow = qb*128 + (ty<<2) + (i & 3) + ((i >> 2) << 6);
        float4 ov;
        ov.x = o[i][0]*invl; ov.y = o[i][1]*invl;
        ov.z = o[i][2]*invl; ov.w = o[i][3]*invl;
        *(float4*)&g_C[(size_t)b*S_*D_ + (size_t)srow*D_ + h*DH_ + (tx<<2)] = ov;
    }
}

// ---------------------------------------------------------------------------
extern "C" void kernel_launch(void* const* d_in, const int* in_sizes, int n_in,
                              void* d_out, int out_size)
{
    const float* q  = (const float*)d_in[0];
    const float* k  = (const float*)d_in[1];
    const float* v  = (const float*)d_in[2];
    const float* Wq = (const float*)d_in[3];
    const float* bq = (const float*)d_in[4];
    const float* Wk = (const float*)d_in[5];
    const float* bk = (const float*)d_in[6];
    const float* Wv = (const float*)d_in[7];
    const float* bv = (const float*)d_in[8];
    const float* Wo = (const float*)d_in[9];
    const float* bo = (const float*)d_in[10];
    float* out = (float*)d_out;

    float *Qp, *Kp, *Vp, *Cp;
    cudaGetSymbolAddress((void**)&Qp, g_Q);
    cudaGetSymbolAddress((void**)&Kp, g_K);
    cudaGetSymbolAddress((void**)&Vp, g_V);
    cudaGetSymbolAddress((void**)&Cp, g_C);

    dim3 gg(D_/128, MTOT/128), bb(256);
    gemm_bias_kernel<<<gg, bb>>>(q, Wq, bq, Qp);
    gemm_bias_kernel<<<gg, bb>>>(k, Wk, bk, Kp);
    gemm_bias_kernel<<<gg, bb>>>(v, Wv, bv, Vp);

    rope_kernel<<<(B_*S_*H_*32)/256, 256>>>();

    int smem = (2*64*132 + 64*64) * (int)sizeof(float);  // 83968 B
    cudaFuncSetAttribute(attn_kernel, cudaFuncAttributeMaxDynamicSharedMemorySize, smem);
    attn_kernel<<<dim3(S_/128, B_*H_), 256, smem>>>();

    gemm_bias_kernel<<<gg, bb>>>(Cp, Wo, bo, out);
}

// round 4
// speedup vs baseline: 1.5344x; 1.2478x over previous
#include <cuda_runtime.h>
#include <cuda_bf16.h>
#include <math.h>
#include <stdint.h>

#define B_  2
#define S_  2048
#define D_  1024
#define H_  16
#define DH_ 64
#define MTOT (B_*S_)   // 4096

__device__ float g_Q[MTOT*D_];
__device__ float g_K[MTOT*D_];
__device__ float g_V[MTOT*D_];
__device__ float g_C[MTOT*D_];
__device__ __nv_bfloat16 g_Xhi[MTOT*D_];
__device__ __nv_bfloat16 g_Xlo[MTOT*D_];
__device__ __nv_bfloat16 g_Whi[D_*D_];
__device__ __nv_bfloat16 g_Wlo[D_*D_];

#define SW128(o) ((o) ^ (((o) >> 3) & 0x70))

static __device__ __forceinline__ uint32_t s2u(const void* p) {
    uint32_t a;
    asm("{ .reg .u64 t; cvta.to.shared.u64 t, %1; cvt.u32.u64 %0, t; }" : "=r"(a) : "l"(p));
    return a;
}

static __device__ __forceinline__ void ldm4(uint32_t* r, uint32_t addr) {
    asm volatile("ldmatrix.sync.aligned.m8n8.x4.shared.b16 {%0,%1,%2,%3}, [%4];"
        : "=r"(r[0]), "=r"(r[1]), "=r"(r[2]), "=r"(r[3]) : "r"(addr));
}

static __device__ __forceinline__ void mma_bf16(float* c, const uint32_t* a, const uint32_t* b) {
    asm volatile("mma.sync.aligned.m16n8k16.row.col.f32.bf16.bf16.f32 "
        "{%0,%1,%2,%3}, {%4,%5,%6,%7}, {%8,%9}, {%0,%1,%2,%3};"
        : "+f"(c[0]), "+f"(c[1]), "+f"(c[2]), "+f"(c[3])
        : "r"(a[0]), "r"(a[1]), "r"(a[2]), "r"(a[3]), "r"(b[0]), "r"(b[1]));
}

// ===========================================================================
// fp32 -> bf16 hi/lo split
// ===========================================================================
__global__ __launch_bounds__(256) void split_kernel(
    const float* __restrict__ x, __nv_bfloat16* __restrict__ hi,
    __nv_bfloat16* __restrict__ lo)
{
    int i = blockIdx.x * 256 + threadIdx.x;
    float4 v = ((const float4*)x)[i];
    __nv_bfloat16 h0 = __float2bfloat16(v.x), h1 = __float2bfloat16(v.y);
    __nv_bfloat16 h2 = __float2bfloat16(v.z), h3 = __float2bfloat16(v.w);
    __nv_bfloat16 l0 = __float2bfloat16(v.x - __bfloat162float(h0));
    __nv_bfloat16 l1 = __float2bfloat16(v.y - __bfloat162float(h1));
    __nv_bfloat16 l2 = __float2bfloat16(v.z - __bfloat162float(h2));
    __nv_bfloat16 l3 = __float2bfloat16(v.w - __bfloat162float(h3));
    __nv_bfloat162* hp = (__nv_bfloat162*)hi;
    __nv_bfloat162* lp = (__nv_bfloat162*)lo;
    hp[2*i]   = __halves2bfloat162(h0, h1);
    hp[2*i+1] = __halves2bfloat162(h2, h3);
    lp[2*i]   = __halves2bfloat162(l0, l1);
    lp[2*i+1] = __halves2bfloat162(l2, l3);
}

// ===========================================================================
// Split-bf16 tensor-core GEMM via mma.sync: Y[M,1024] = X @ W^T + bias
// CTA 128x128, BK=64, 256 threads (8 warps: 4m x 2n), double-buffered smem.
// smem per buffer: Ahi(16K) Alo(16K) Bhi(16K) Blo(16K) = 64K; x2 = 128K.
// ===========================================================================
__device__ __forceinline__ void load_chunk(
    char* smem, int bufi, int kc,
    const __nv_bfloat16* __restrict__ Ahi, const __nv_bfloat16* __restrict__ Alo,
    const __nv_bfloat16* __restrict__ Bhi, const __nv_bfloat16* __restrict__ Blo,
    int m0, int n0, int tid)
{
    char* base = smem + bufi * 65536;
    #pragma unroll
    for (int i = 0; i < 4; i++) {
        int idx = tid + i * 256;      // 0..1023
        int row = idx >> 3;           // 0..127
        int c8  = idx & 7;            // 16B group within 128B row
        uint32_t so = SW128((uint32_t)(row * 128 + c8 * 16));
        size_t ga = (size_t)(m0 + row) * D_ + kc * 64 + c8 * 8;
        size_t gb = (size_t)(n0 + row) * D_ + kc * 64 + c8 * 8;
        *(uint4*)(base + so)         = *(const uint4*)(Ahi + ga);
        *(uint4*)(base + 16384 + so) = *(const uint4*)(Alo + ga);
        *(uint4*)(base + 32768 + so) = *(const uint4*)(Bhi + gb);
        *(uint4*)(base + 49152 + so) = *(const uint4*)(Blo + gb);
    }
}

__global__ __launch_bounds__(256, 1) void gemm_mma_kernel(
    const __nv_bfloat16* __restrict__ Ahi, const __nv_bfloat16* __restrict__ Alo,
    const __nv_bfloat16* __restrict__ Bhi, const __nv_bfloat16* __restrict__ Blo,
    const float* __restrict__ bias, float* __restrict__ Y)
{
    extern __shared__ char smem[];
    const int tid = threadIdx.x;
    const int lane = tid & 31, wid = tid >> 5;
    const int wm = wid & 3;          // m warp: 0..3 (32 rows each)
    const int wn = wid >> 2;         // n warp: 0..1 (64 cols each)
    const int m0 = blockIdx.y * 128, n0 = blockIdx.x * 128;
    const uint32_t sb = s2u(smem);

    // per-lane ldmatrix addressing pieces (SW128 on 128B rows)
    const uint32_t swx = (uint32_t)((lane & 7) << 4);
    const int aRowBase = wm * 32 + (lane & 15);          // + mt*16
    const uint32_t aKl = (uint32_t)((lane >> 4) << 4);   // 0 or 16
    const int bRowBase = wn * 64 + ((lane >> 4) << 3) + (lane & 7);  // + ng*16
    const uint32_t bKl = (uint32_t)(((lane >> 3) & 1) << 4);

    float acc[2][8][4];
    #pragma unroll
    for (int mt = 0; mt < 2; mt++)
        #pragma unroll
        for (int nt = 0; nt < 8; nt++)
            #pragma unroll
            for (int r = 0; r < 4; r++) acc[mt][nt][r] = 0.f;

    load_chunk(smem, 0, 0, Ahi, Alo, Bhi, Blo, m0, n0, tid);
    __syncthreads();

    int buf = 0;
    #pragma unroll 1
    for (int kc = 0; kc < 16; kc++) {
        if (kc + 1 < 16)
            load_chunk(smem, buf ^ 1, kc + 1, Ahi, Alo, Bhi, Blo, m0, n0, tid);

        const uint32_t bofs = sb + (uint32_t)buf * 65536u;
        #pragma unroll
        for (int kk = 0; kk < 4; kk++) {
            const uint32_t kb = (uint32_t)(kk << 5);
            uint32_t ah[2][4], al[2][4];
            #pragma unroll
            for (int mt = 0; mt < 2; mt++) {
                uint32_t rowoff = (uint32_t)(aRowBase + mt * 16) * 128u;
                uint32_t cofs = (kb + aKl) ^ swx;
                ldm4(ah[mt], bofs + rowoff + cofs);
                ldm4(al[mt], bofs + 16384u + rowoff + cofs);
            }
            uint32_t bh[4][4], bl[4][4];
            #pragma unroll
            for (int ng = 0; ng < 4; ng++) {
                uint32_t rowoff = (uint32_t)(bRowBase + ng * 16) * 128u;
                uint32_t cofs = (kb + bKl) ^ swx;
                ldm4(bh[ng], bofs + 32768u + rowoff + cofs);
                ldm4(bl[ng], bofs + 49152u + rowoff + cofs);
            }
            #pragma unroll
            for (int mt = 0; mt < 2; mt++)
                #pragma unroll
                for (int ng = 0; ng < 4; ng++) {
                    mma_bf16(acc[mt][2*ng],   ah[mt], &bh[ng][0]);
                    mma_bf16(acc[mt][2*ng+1], ah[mt], &bh[ng][2]);
                    mma_bf16(acc[mt][2*ng],   ah[mt], &bl[ng][0]);
                    mma_bf16(acc[mt][2*ng+1], ah[mt], &bl[ng][2]);
                    mma_bf16(acc[mt][2*ng],   al[mt], &bh[ng][0]);
                    mma_bf16(acc[mt][2*ng+1], al[mt], &bh[ng][2]);
                }
        }
        __syncthreads();
        buf ^= 1;
    }

    // Epilogue: add bias, store
    #pragma unroll
    for (int mt = 0; mt < 2; mt++) {
        int r0 = m0 + wm * 32 + mt * 16 + (lane >> 2);
        #pragma unroll
        for (int nt = 0; nt < 8; nt++) {
            int c = n0 + wn * 64 + nt * 8 + ((lane & 3) << 1);
            float2 bb = *(const float2*)&bias[c];
            float2 v0 = make_float2(acc[mt][nt][0] + bb.x, acc[mt][nt][1] + bb.y);
            float2 v1 = make_float2(acc[mt][nt][2] + bb.x, acc[mt][nt][3] + bb.y);
            *(float2*)&Y[(size_t)r0 * D_ + c]       = v0;
            *(float2*)&Y[(size_t)(r0 + 8) * D_ + c] = v1;
        }
    }
}

// ===========================================================================
// RoPE (reference variant), in-place on g_Q and g_K.
// ===========================================================================
__global__ __launch_bounds__(256) void rope_kernel()
{
    __shared__ float sinv[32];
    if (threadIdx.x < 32) {
        float coef = -(4.0f * logf(10.0f)) / 64.0f;
        float arg  = (float)(2 * threadIdx.x) * coef;
        sinv[threadIdx.x] = (float)exp((double)arg);
    }
    __syncthreads();

    int idx = blockIdx.x * blockDim.x + threadIdx.x;
    int j = idx & 31;
    int t = idx >> 5;
    int h = t & (H_ - 1);
    int rowi = t >> 4;
    int s = rowi & (S_ - 1);

    float ang = (float)s * sinv[j];
    float sn, cs;
    sincosf(ang, &sn, &cs);

    size_t base = (size_t)rowi * D_ + h * DH_ + 2 * j;
    float x1 = g_Q[base], x2 = g_Q[base+1];
    g_Q[base]   =  x1 * sn - x2 * cs;
    g_Q[base+1] = -x1 * cs - x2 * sn;
    x1 = g_K[base]; x2 = g_K[base+1];
    g_K[base]   =  x1 * sn - x2 * cs;
    g_K[base+1] = -x1 * cs - x2 * sn;
}

// ===========================================================================
// Causal flash attention (fp32 FFMA). Q tile 128, K tile 64, 8x4 micro-tile.
// ===========================================================================
__global__ __launch_bounds__(256, 2) void attn_kernel()
{
    extern __shared__ float sm[];
    float* sQt = sm;                 // 64*132
    float* sKP = sm + 64*132;        // 64*132
    float* sV  = sm + 2*64*132;      // 64*64

    const int qb = gridDim.x - 1 - blockIdx.x;
    const int bh = blockIdx.y;
    const int b = bh >> 4, h = bh & 15;
    const int tid = threadIdx.x, tx = tid & 15, ty = tid >> 4;
    const size_t headoff = (size_t)b * S_ * D_ + (size_t)h * DH_;
    const float* Qg = g_Q + headoff;
    const float* Kg = g_K + headoff;
    const float* Vg = g_V + headoff;

    const int lr = tid >> 4;
    const int ld = (tid & 15) << 2;

    #pragma unroll
    for (int w = 0; w < 8; w++) {
        int m = lr + 16*w;
        float4 qv = *(const float4*)&Qg[(size_t)(qb*128+m)*D_ + ld];
        sQt[(ld+0)*132+m]=qv.x; sQt[(ld+1)*132+m]=qv.y;
        sQt[(ld+2)*132+m]=qv.z; sQt[(ld+3)*132+m]=qv.w;
    }

    float m_r[8], l_r[8], o[8][4];
    #pragma unroll
    for (int i = 0; i < 8; i++) {
        m_r[i] = -1e30f; l_r[i] = 0.f;
        #pragma unroll
        for (int j = 0; j < 4; j++) o[i][j] = 0.f;
    }

    const int nkb = 2*qb + 2;
    for (int kb = 0; kb < nkb; kb++) {
        #pragma unroll
        for (int w = 0; w < 4; w++) {
            int c = lr + 16*w;
            float4 kv = *(const float4*)&Kg[(size_t)(kb*64+c)*D_ + ld];
            sKP[(ld+0)*132+c]=kv.x; sKP[(ld+1)*132+c]=kv.y;
            sKP[(ld+2)*132+c]=kv.z; sKP[(ld+3)*132+c]=kv.w;
            float4 vv = *(const float4*)&Vg[(size_t)(kb*64+c)*D_ + ld];
            *(float4*)&sV[c*64+ld] = vv;
        }
        __syncthreads();

        float s_[8][4];
        #pragma unroll
        for (int i = 0; i < 8; i++)
            #pragma unroll
            for (int j = 0; j < 4; j++) s_[i][j] = 0.f;
        #pragma unroll 4
        for (int d = 0; d < 64; d++) {
            float4 a  = *(const float4*)&sQt[d*132 + (ty<<2)];
            float4 a2 = *(const float4*)&sQt[d*132 + (ty<<2) + 64];
            float4 bb = *(const float4*)&sKP[d*132 + (tx<<2)];
            float av[8] = {a.x,a.y,a.z,a.w, a2.x,a2.y,a2.z,a2.w};
            float bv[4] = {bb.x,bb.y,bb.z,bb.w};
            #pragma unroll
            for (int i = 0; i < 8; i++)
                #pragma unroll
                for (int j = 0; j < 4; j++)
                    s_[i][j] = fmaf(av[i], bv[j], s_[i][j]);
        }
        __syncthreads();

        if (kb >= 2*qb) {
            #pragma unroll
            for (int i = 0; i < 8; i++) {
                int rg = qb*128 + (ty<<2) + (i & 3) + ((i >> 2) << 6);
                #pragma unroll
                for (int j = 0; j < 4; j++) {
                    int cg = kb*64 + (tx<<2) + j;
                    if (cg > rg) s_[i][j] = -1e30f;
                }
            }
        }

        #pragma unroll
        for (int i = 0; i < 8; i++) {
            float mx = fmaxf(fmaxf(s_[i][0], s_[i][1]), fmaxf(s_[i][2], s_[i][3]));
            #pragma unroll
            for (int off = 8; off >= 1; off >>= 1)
                mx = fmaxf(mx, __shfl_xor_sync(0xffffffffu, mx, off));
            float mn = fmaxf(m_r[i], mx);
            float alpha = __expf(m_r[i] - mn);
            float ps = 0.f;
            #pragma unroll
            for (int j = 0; j < 4; j++) {
                float p = __expf(s_[i][j] - mn);
                s_[i][j] = p; ps += p;
            }
            #pragma unroll
            for (int off = 8; off >= 1; off >>= 1)
                ps += __shfl_xor_sync(0xffffffffu, ps, off);
            l_r[i] = l_r[i]*alpha + ps;
            m_r[i] = mn;
            int row = (ty<<2) + (i & 3) + ((i >> 2) << 6);
            #pragma unroll
            for (int j = 0; j < 4; j++) {
                o[i][j] *= alpha;
                sKP[((tx<<2)+j)*132 + row] = s_[i][j];
            }
        }
        __syncthreads();

        #pragma unroll 4
        for (int c = 0; c < 64; c++) {
            float4 a  = *(const float4*)&sKP[c*132 + (ty<<2)];
            float4 a2 = *(const float4*)&sKP[c*132 + (ty<<2) + 64];
            float4 vv = *(const float4*)&sV[c*64 + (tx<<2)];
            float av[8] = {a.x,a.y,a.z,a.w, a2.x,a2.y,a2.z,a2.w};
            float bv[4] = {vv.x,vv.y,vv.z,vv.w};
            #pragma unroll
            for (int i = 0; i < 8; i++)
                #pragma unroll
                for (int j = 0; j < 4; j++)
                    o[i][j] = fmaf(av[i], bv[j], o[i][j]);
        }
        __syncthreads();
    }

    #pragma unroll
    for (int i = 0; i < 8; i++) {
        float invl = 1.0f / l_r[i];
        int srow = qb*128 + (ty<<2) + (i & 3) + ((i >> 2) << 6);
        float4 ov;
        ov.x = o[i][0]*invl; ov.y = o[i][1]*invl;
        ov.z = o[i][2]*invl; ov.w = o[i][3]*invl;
        *(float4*)&g_C[(size_t)b*S_*D_ + (size_t)srow*D_ + h*DH_ + (tx<<2)] = ov;
    }
}

// ===========================================================================
extern "C" void kernel_launch(void* const* d_in, const int* in_sizes, int n_in,
                              void* d_out, int out_size)
{
    const float* q  = (const float*)d_in[0];
    const float* k  = (const float*)d_in[1];
    const float* v  = (const float*)d_in[2];
    const float* Wq = (const float*)d_in[3];
    const float* bq = (const float*)d_in[4];
    const float* Wk = (const float*)d_in[5];
    const float* bk = (const float*)d_in[6];
    const float* Wv = (const float*)d_in[7];
    const float* bv = (const float*)d_in[8];
    const float* Wo = (const float*)d_in[9];
    const float* bo = (const float*)d_in[10];
    float* out = (float*)d_out;

    float *Qp, *Kp, *Vp, *Cp;
    cudaGetSymbolAddress((void**)&Qp, g_Q);
    cudaGetSymbolAddress((void**)&Kp, g_K);
    cudaGetSymbolAddress((void**)&Vp, g_V);
    cudaGetSymbolAddress((void**)&Cp, g_C);
    __nv_bfloat16 *Xhi, *Xlo, *Whi, *Wlo;
    cudaGetSymbolAddress((void**)&Xhi, g_Xhi);
    cudaGetSymbolAddress((void**)&Xlo, g_Xlo);
    cudaGetSymbolAddress((void**)&Whi, g_Whi);
    cudaGetSymbolAddress((void**)&Wlo, g_Wlo);

    const int gsmem = 2 * 65536;  // 131072
    cudaFuncSetAttribute(gemm_mma_kernel, cudaFuncAttributeMaxDynamicSharedMemorySize, gsmem);
    dim3 gt(D_/128, MTOT/128);           // (8, 32)
    const int NXB = (MTOT*D_/4)/256;
    const int NWB = (D_*D_/4)/256;

    split_kernel<<<NXB, 256>>>(q, Xhi, Xlo);
    split_kernel<<<NWB, 256>>>(Wq, Whi, Wlo);
    gemm_mma_kernel<<<gt, 256, gsmem>>>(Xhi, Xlo, Whi, Wlo, bq, Qp);

    split_kernel<<<NXB, 256>>>(k, Xhi, Xlo);
    split_kernel<<<NWB, 256>>>(Wk, Whi, Wlo);
    gemm_mma_kernel<<<gt, 256, gsmem>>>(Xhi, Xlo, Whi, Wlo, bk, Kp);

    split_kernel<<<NXB, 256>>>(v, Xhi, Xlo);
    split_kernel<<<NWB, 256>>>(Wv, Whi, Wlo);
    gemm_mma_kernel<<<gt, 256, gsmem>>>(Xhi, Xlo, Whi, Wlo, bv, Vp);

    rope_kernel<<<(B_*S_*H_*32)/256, 256>>>();

    int asmem = (2*64*132 + 64*64) * (int)sizeof(float);
    cudaFuncSetAttribute(attn_kernel, cudaFuncAttributeMaxDynamicSharedMemorySize, asmem);
    attn_kernel<<<dim3(S_/128, B_*H_), 256, asmem>>>();

    split_kernel<<<NXB, 256>>>(Cp, Xhi, Xlo);
    split_kernel<<<NWB, 256>>>(Wo, Whi, Wlo);
    gemm_mma_kernel<<<gt, 256, gsmem>>>(Xhi, Xlo, Whi, Wlo, bo, out);
}

// round 5
// speedup vs baseline: 2.7638x; 1.8013x over previous
#include <cuda_runtime.h>
#include <cuda_bf16.h>
#include <math.h>
#include <stdint.h>

#define B_  2
#define S_  2048
#define D_  1024
#define H_  16
#define DH_ 64
#define MTOT (B_*S_)   // 4096

__device__ float g_Q[MTOT*D_];
__device__ float g_K[MTOT*D_];
__device__ float g_V[MTOT*D_];
__device__ float g_C[MTOT*D_];
__device__ __nv_bfloat16 g_Xhi[MTOT*D_];
__device__ __nv_bfloat16 g_Xlo[MTOT*D_];
__device__ __nv_bfloat16 g_Whi[D_*D_];
__device__ __nv_bfloat16 g_Wlo[D_*D_];
// attention operand splits
__device__ __nv_bfloat16 g_Qhi[MTOT*D_];
__device__ __nv_bfloat16 g_Qlo[MTOT*D_];
__device__ __nv_bfloat16 g_Khi[MTOT*D_];
__device__ __nv_bfloat16 g_Klo[MTOT*D_];
__device__ __nv_bfloat16 g_Vthi[MTOT*D_];   // [bh][d][s]
__device__ __nv_bfloat16 g_Vtlo[MTOT*D_];

#define SW128(o) ((o) ^ (((o) >> 3) & 0x70))

static __device__ __forceinline__ uint32_t s2u(const void* p) {
    uint32_t a;
    asm("{ .reg .u64 t; cvta.to.shared.u64 t, %1; cvt.u32.u64 %0, t; }" : "=r"(a) : "l"(p));
    return a;
}
static __device__ __forceinline__ void ldm4(uint32_t* r, uint32_t addr) {
    asm volatile("ldmatrix.sync.aligned.m8n8.x4.shared.b16 {%0,%1,%2,%3}, [%4];"
        : "=r"(r[0]), "=r"(r[1]), "=r"(r[2]), "=r"(r[3]) : "r"(addr));
}
static __device__ __forceinline__ void mma_bf16(float* c, const uint32_t* a, const uint32_t* b) {
    asm volatile("mma.sync.aligned.m16n8k16.row.col.f32.bf16.bf16.f32 "
        "{%0,%1,%2,%3}, {%4,%5,%6,%7}, {%8,%9}, {%0,%1,%2,%3};"
        : "+f"(c[0]), "+f"(c[1]), "+f"(c[2]), "+f"(c[3])
        : "r"(a[0]), "r"(a[1]), "r"(a[2]), "r"(a[3]), "r"(b[0]), "r"(b[1]));
}
static __device__ __forceinline__ void splitpk(float x, float y, uint32_t& hi, uint32_t& lo) {
    __nv_bfloat16 hx = __float2bfloat16(x), hy = __float2bfloat16(y);
    float rx = x - __bfloat162float(hx), ry = y - __bfloat162float(hy);
    __nv_bfloat16 lx = __float2bfloat16(rx), ly = __float2bfloat16(ry);
    hi = (uint32_t)__bfloat16_as_ushort(hx) | ((uint32_t)__bfloat16_as_ushort(hy) << 16);
    lo = (uint32_t)__bfloat16_as_ushort(lx) | ((uint32_t)__bfloat16_as_ushort(ly) << 16);
}

// ===========================================================================
// fp32 -> bf16 hi/lo split (for projection GEMM operands)
// ===========================================================================
__global__ __launch_bounds__(256) void split_kernel(
    const float* __restrict__ x, __nv_bfloat16* __restrict__ hi,
    __nv_bfloat16* __restrict__ lo)
{
    int i = blockIdx.x * 256 + threadIdx.x;
    float4 v = ((const float4*)x)[i];
    uint32_t h0, l0, h1, l1;
    splitpk(v.x, v.y, h0, l0);
    splitpk(v.z, v.w, h1, l1);
    ((uint2*)hi)[i] = make_uint2(h0, h1);
    ((uint2*)lo)[i] = make_uint2(l0, l1);
}

// ===========================================================================
// Split-bf16 tensor-core GEMM via mma.sync: Y[M,1024] = X @ W^T + bias
// (unchanged from round 4 — proven)
// ===========================================================================
__device__ __forceinline__ void load_chunk(
    char* smem, int bufi, int kc,
    const __nv_bfloat16* __restrict__ Ahi, const __nv_bfloat16* __restrict__ Alo,
    const __nv_bfloat16* __restrict__ Bhi, const __nv_bfloat16* __restrict__ Blo,
    int m0, int n0, int tid)
{
    char* base = smem + bufi * 65536;
    #pragma unroll
    for (int i = 0; i < 4; i++) {
        int idx = tid + i * 256;
        int row = idx >> 3;
        int c8  = idx & 7;
        uint32_t so = SW128((uint32_t)(row * 128 + c8 * 16));
        size_t ga = (size_t)(m0 + row) * D_ + kc * 64 + c8 * 8;
        size_t gb = (size_t)(n0 + row) * D_ + kc * 64 + c8 * 8;
        *(uint4*)(base + so)         = *(const uint4*)(Ahi + ga);
        *(uint4*)(base + 16384 + so) = *(const uint4*)(Alo + ga);
        *(uint4*)(base + 32768 + so) = *(const uint4*)(Bhi + gb);
        *(uint4*)(base + 49152 + so) = *(const uint4*)(Blo + gb);
    }
}

__global__ __launch_bounds__(256, 1) void gemm_mma_kernel(
    const __nv_bfloat16* __restrict__ Ahi, const __nv_bfloat16* __restrict__ Alo,
    const __nv_bfloat16* __restrict__ Bhi, const __nv_bfloat16* __restrict__ Blo,
    const float* __restrict__ bias, float* __restrict__ Y)
{
    extern __shared__ char smem[];
    const int tid = threadIdx.x;
    const int lane = tid & 31, wid = tid >> 5;
    const int wm = wid & 3;
    const int wn = wid >> 2;
    const int m0 = blockIdx.y * 128, n0 = blockIdx.x * 128;
    const uint32_t sb = s2u(smem);

    const uint32_t swx = (uint32_t)((lane & 7) << 4);
    const int aRowBase = wm * 32 + (lane & 15);
    const uint32_t aKl = (uint32_t)((lane >> 4) << 4);
    const int bRowBase = wn * 64 + ((lane >> 4) << 3) + (lane & 7);
    const uint32_t bKl = (uint32_t)(((lane >> 3) & 1) << 4);

    float acc[2][8][4];
    #pragma unroll
    for (int mt = 0; mt < 2; mt++)
        #pragma unroll
        for (int nt = 0; nt < 8; nt++)
            #pragma unroll
            for (int r = 0; r < 4; r++) acc[mt][nt][r] = 0.f;

    load_chunk(smem, 0, 0, Ahi, Alo, Bhi, Blo, m0, n0, tid);
    __syncthreads();

    int buf = 0;
    #pragma unroll 1
    for (int kc = 0; kc < 16; kc++) {
        if (kc + 1 < 16)
            load_chunk(smem, buf ^ 1, kc + 1, Ahi, Alo, Bhi, Blo, m0, n0, tid);

        const uint32_t bofs = sb + (uint32_t)buf * 65536u;
        #pragma unroll
        for (int kk = 0; kk < 4; kk++) {
            const uint32_t kb = (uint32_t)(kk << 5);
            uint32_t ah[2][4], al[2][4];
            #pragma unroll
            for (int mt = 0; mt < 2; mt++) {
                uint32_t rowoff = (uint32_t)(aRowBase + mt * 16) * 128u;
                uint32_t cofs = (kb + aKl) ^ swx;
                ldm4(ah[mt], bofs + rowoff + cofs);
                ldm4(al[mt], bofs + 16384u + rowoff + cofs);
            }
            uint32_t bh[4][4], bl[4][4];
            #pragma unroll
            for (int ng = 0; ng < 4; ng++) {
                uint32_t rowoff = (uint32_t)(bRowBase + ng * 16) * 128u;
                uint32_t cofs = (kb + bKl) ^ swx;
                ldm4(bh[ng], bofs + 32768u + rowoff + cofs);
                ldm4(bl[ng], bofs + 49152u + rowoff + cofs);
            }
            #pragma unroll
            for (int mt = 0; mt < 2; mt++)
                #pragma unroll
                for (int ng = 0; ng < 4; ng++) {
                    mma_bf16(acc[mt][2*ng],   ah[mt], &bh[ng][0]);
                    mma_bf16(acc[mt][2*ng+1], ah[mt], &bh[ng][2]);
                    mma_bf16(acc[mt][2*ng],   ah[mt], &bl[ng][0]);
                    mma_bf16(acc[mt][2*ng+1], ah[mt], &bl[ng][2]);
                    mma_bf16(acc[mt][2*ng],   al[mt], &bh[ng][0]);
                    mma_bf16(acc[mt][2*ng+1], al[mt], &bh[ng][2]);
                }
        }
        __syncthreads();
        buf ^= 1;
    }

    #pragma unroll
    for (int mt = 0; mt < 2; mt++) {
        int r0 = m0 + wm * 32 + mt * 16 + (lane >> 2);
        #pragma unroll
        for (int nt = 0; nt < 8; nt++) {
            int c = n0 + wn * 64 + nt * 8 + ((lane & 3) << 1);
            float2 bb = *(const float2*)&bias[c];
            *(float2*)&Y[(size_t)r0 * D_ + c] =
                make_float2(acc[mt][nt][0] + bb.x, acc[mt][nt][1] + bb.y);
            *(float2*)&Y[(size_t)(r0 + 8) * D_ + c] =
                make_float2(acc[mt][nt][2] + bb.x, acc[mt][nt][3] + bb.y);
        }
    }
}

// ===========================================================================
// RoPE in-place semantics, but emits bf16 hi/lo splits of rotated Q,K.
// ===========================================================================
__global__ __launch_bounds__(256) void rope_kernel()
{
    __shared__ float sinv[32];
    if (threadIdx.x < 32) {
        float coef = -(4.0f * logf(10.0f)) / 64.0f;
        float arg  = (float)(2 * threadIdx.x) * coef;
        sinv[threadIdx.x] = (float)exp((double)arg);
    }
    __syncthreads();

    int idx = blockIdx.x * blockDim.x + threadIdx.x;
    int j = idx & 31;
    int t = idx >> 5;
    int h = t & (H_ - 1);
    int rowi = t >> 4;
    int s = rowi & (S_ - 1);

    float ang = (float)s * sinv[j];
    float sn, cs;
    sincosf(ang, &sn, &cs);

    size_t base = (size_t)rowi * D_ + h * DH_ + 2 * j;
    float x1 = g_Q[base], x2 = g_Q[base+1];
    float y1 =  x1 * sn - x2 * cs;
    float y2 = -x1 * cs - x2 * sn;
    uint32_t hi, lo;
    splitpk(y1, y2, hi, lo);
    *(uint32_t*)&g_Qhi[base] = hi;
    *(uint32_t*)&g_Qlo[base] = lo;

    x1 = g_K[base]; x2 = g_K[base+1];
    y1 =  x1 * sn - x2 * cs;
    y2 = -x1 * cs - x2 * sn;
    splitpk(y1, y2, hi, lo);
    *(uint32_t*)&g_Khi[base] = hi;
    *(uint32_t*)&g_Klo[base] = lo;
}

// ===========================================================================
// V transpose + split: g_V [b,s,h,d] -> g_Vt{hi,lo} [bh, d, s]
// Block: (s-tile 64) x (bh). 64x64 tile through smem.
// ===========================================================================
__global__ __launch_bounds__(256) void vtrans_kernel()
{
    __shared__ float sst[64][65];
    const int tid = threadIdx.x;
    const int st = blockIdx.x, bh = blockIdx.y;
    const int b = bh >> 4, h = bh & 15;

    #pragma unroll
    for (int it = 0; it < 4; it++) {
        int r = it * 16 + (tid >> 4);
        int c = (tid & 15) << 2;
        float4 v = *(const float4*)&g_V[(size_t)(b*S_ + st*64 + r)*D_ + h*DH_ + c];
        sst[r][c+0] = v.x; sst[r][c+1] = v.y; sst[r][c+2] = v.z; sst[r][c+3] = v.w;
    }
    __syncthreads();

    const int d = tid >> 2;
    const int cb = (tid & 3) << 4;
    uint32_t hi[8], lo[8];
    #pragma unroll
    for (int i = 0; i < 8; i++)
        splitpk(sst[cb + 2*i][d], sst[cb + 2*i + 1][d], hi[i], lo[i]);
    size_t ga = (size_t)(bh * 64 + d) * S_ + st * 64 + cb;
    *(uint4*)&g_Vthi[ga]     = make_uint4(hi[0], hi[1], hi[2], hi[3]);
    *(uint4*)&g_Vthi[ga + 8] = make_uint4(hi[4], hi[5], hi[6], hi[7]);
    *(uint4*)&g_Vtlo[ga]     = make_uint4(lo[0], lo[1], lo[2], lo[3]);
    *(uint4*)&g_Vtlo[ga + 8] = make_uint4(lo[4], lo[5], lo[6], lo[7]);
}

// ===========================================================================
// Causal flash attention, split-bf16 mma.sync.
// Q tile 128x64, K/V tiles 64. 8 warps, each 16 rows. Softmax in fragments.
// smem: Qhi 16K | Qlo 16K | Khi 8K | Klo 8K | Vhi 8K | Vlo 8K = 64K
// ===========================================================================
__global__ __launch_bounds__(256, 1) void attn_mma_kernel()
{
    extern __shared__ char smA[];
    const uint32_t QHI=0, QLO=16384, KHI=32768, KLO=40960, VHI=49152, VLO=57344;
    const uint32_t sb = s2u(smA);
    const int tid = threadIdx.x, lane = tid & 31, wid = tid >> 5;
    const int qb = gridDim.x - 1 - blockIdx.x;   // long blocks first
    const int bh = blockIdx.y, b = bh >> 4, h = bh & 15;

    // Load Q tile (hi+lo), SW128 rows of 128B
    #pragma unroll
    for (int i = 0; i < 4; i++) {
        int idx = tid + i * 256, row = idx >> 3, c8 = idx & 7;
        uint32_t so = SW128((uint32_t)(row * 128 + c8 * 16));
        size_t ga = (size_t)(b*S_ + qb*128 + row) * D_ + h*DH_ + c8*8;
        *(uint4*)(smA + QHI + so) = *(const uint4*)(g_Qhi + ga);
        *(uint4*)(smA + QLO + so) = *(const uint4*)(g_Qlo + ga);
    }
    __syncthreads();

    const uint32_t swx  = (uint32_t)((lane & 7) << 4);
    const uint32_t aRow = (uint32_t)(wid * 16 + (lane & 15));
    const uint32_t aKl  = (uint32_t)((lane >> 4) << 4);
    const uint32_t bRow = (uint32_t)(((lane >> 4) << 3) + (lane & 7));
    const uint32_t bKl  = (uint32_t)(((lane >> 3) & 1) << 4);

    // Preload Q fragments (constant across k-tiles)
    uint32_t qh[4][4], ql[4][4];
    #pragma unroll
    for (int kk = 0; kk < 4; kk++) {
        uint32_t cofs = ((uint32_t)(kk << 5) + aKl) ^ swx;
        ldm4(qh[kk], sb + QHI + aRow * 128u + cofs);
        ldm4(ql[kk], sb + QLO + aRow * 128u + cofs);
    }

    float m_a = -1e30f, m_b = -1e30f, l_a = 0.f, l_b = 0.f;
    float oc[8][4];
    #pragma unroll
    for (int t = 0; t < 8; t++)
        #pragma unroll
        for (int r = 0; r < 4; r++) oc[t][r] = 0.f;

    const int nkb = 2 * qb + 2;
    #pragma unroll 1
    for (int kb = 0; kb < nkb; kb++) {
        // Load K tile (hi/lo) and Vt tile (hi/lo)
        #pragma unroll
        for (int i = 0; i < 2; i++) {
            int idx = tid + i * 256, row = idx >> 3, c8 = idx & 7;
            uint32_t so = SW128((uint32_t)(row * 128 + c8 * 16));
            size_t gk = (size_t)(b*S_ + kb*64 + row) * D_ + h*DH_ + c8*8;
            size_t gv = (size_t)(bh*64 + row) * S_ + kb*64 + c8*8;
            *(uint4*)(smA + KHI + so) = *(const uint4*)(g_Khi + gk);
            *(uint4*)(smA + KLO + so) = *(const uint4*)(g_Klo + gk);
            *(uint4*)(smA + VHI + so) = *(const uint4*)(g_Vthi + gv);
            *(uint4*)(smA + VLO + so) = *(const uint4*)(g_Vtlo + gv);
        }
        __syncthreads();

        // S = Q K^T  (128x64, k=64, 3-term split)
        float sc[8][4];
        #pragma unroll
        for (int t = 0; t < 8; t++)
            #pragma unroll
            for (int r = 0; r < 4; r++) sc[t][r] = 0.f;
        #pragma unroll
        for (int kk = 0; kk < 4; kk++) {
            uint32_t kh[4][4], kl[4][4];
            uint32_t cofs = ((uint32_t)(kk << 5) + bKl) ^ swx;
            #pragma unroll
            for (int ng = 0; ng < 4; ng++) {
                uint32_t ro = (bRow + (uint32_t)(ng * 16)) * 128u;
                ldm4(kh[ng], sb + KHI + ro + cofs);
                ldm4(kl[ng], sb + KLO + ro + cofs);
            }
            #pragma unroll
            for (int ng = 0; ng < 4; ng++) {
                mma_bf16(sc[2*ng],   qh[kk], &kh[ng][0]);
                mma_bf16(sc[2*ng+1], qh[kk], &kh[ng][2]);
                mma_bf16(sc[2*ng],   qh[kk], &kl[ng][0]);
                mma_bf16(sc[2*ng+1], qh[kk], &kl[ng][2]);
                mma_bf16(sc[2*ng],   ql[kk], &kh[ng][0]);
                mma_bf16(sc[2*ng+1], ql[kk], &kh[ng][2]);
            }
        }

        // Causal mask (diagonal tiles only)
        const int rga = qb*128 + wid*16 + (lane >> 2);
        if (kb >= 2*qb) {
            #pragma unroll
            for (int t = 0; t < 8; t++) {
                int cg = kb*64 + t*8 + ((lane & 3) << 1);
                if (cg     > rga)     sc[t][0] = -1e30f;
                if (cg + 1 > rga)     sc[t][1] = -1e30f;
                if (cg     > rga + 8) sc[t][2] = -1e30f;
                if (cg + 1 > rga + 8) sc[t][3] = -1e30f;
            }
        }

        // Online softmax (rows a = rga, b = rga+8), quad reductions
        float mxa = -1e30f, mxb = -1e30f;
        #pragma unroll
        for (int t = 0; t < 8; t++) {
            mxa = fmaxf(mxa, fmaxf(sc[t][0], sc[t][1]));
            mxb = fmaxf(mxb, fmaxf(sc[t][2], sc[t][3]));
        }
        mxa = fmaxf(mxa, __shfl_xor_sync(0xffffffffu, mxa, 1));
        mxa = fmaxf(mxa, __shfl_xor_sync(0xffffffffu, mxa, 2));
        mxb = fmaxf(mxb, __shfl_xor_sync(0xffffffffu, mxb, 1));
        mxb = fmaxf(mxb, __shfl_xor_sync(0xffffffffu, mxb, 2));
        float mna = fmaxf(m_a, mxa), mnb = fmaxf(m_b, mxb);
        float alpa = __expf(m_a - mna), alpb = __expf(m_b - mnb);
        float psa = 0.f, psb = 0.f;
        #pragma unroll
        for (int t = 0; t < 8; t++) {
            sc[t][0] = __expf(sc[t][0] - mna); psa += sc[t][0];
            sc[t][1] = __expf(sc[t][1] - mna); psa += sc[t][1];
            sc[t][2] = __expf(sc[t][2] - mnb); psb += sc[t][2];
            sc[t][3] = __expf(sc[t][3] - mnb); psb += sc[t][3];
        }
        psa += __shfl_xor_sync(0xffffffffu, psa, 1);
        psa += __shfl_xor_sync(0xffffffffu, psa, 2);
        psb += __shfl_xor_sync(0xffffffffu, psb, 1);
        psb += __shfl_xor_sync(0xffffffffu, psb, 2);
        l_a = l_a * alpa + psa;  m_a = mna;
        l_b = l_b * alpb + psb;  m_b = mnb;
        #pragma unroll
        for (int t = 0; t < 8; t++) {
            oc[t][0] *= alpa; oc[t][1] *= alpa;
            oc[t][2] *= alpb; oc[t][3] *= alpb;
        }

        // O += P V  (P split in registers, V split in smem)
        #pragma unroll
        for (int kk = 0; kk < 4; kk++) {
            uint32_t ph[4], pl[4];
            splitpk(sc[2*kk][0],   sc[2*kk][1],   ph[0], pl[0]);
            splitpk(sc[2*kk][2],   sc[2*kk][3],   ph[1], pl[1]);
            splitpk(sc[2*kk+1][0], sc[2*kk+1][1], ph[2], pl[2]);
            splitpk(sc[2*kk+1][2], sc[2*kk+1][3], ph[3], pl[3]);
            uint32_t vh[4][4], vl[4][4];
            uint32_t cofs = ((uint32_t)(kk << 5) + bKl) ^ swx;
            #pragma unroll
            for (int ng = 0; ng < 4; ng++) {
                uint32_t ro = (bRow + (uint32_t)(ng * 16)) * 128u;
                ldm4(vh[ng], sb + VHI + ro + cofs);
                ldm4(vl[ng], sb + VLO + ro + cofs);
            }
            #pragma unroll
            for (int ng = 0; ng < 4; ng++) {
                mma_bf16(oc[2*ng],   ph, &vh[ng][0]);
                mma_bf16(oc[2*ng+1], ph, &vh[ng][2]);
                mma_bf16(oc[2*ng],   ph, &vl[ng][0]);
                mma_bf16(oc[2*ng+1], ph, &vl[ng][2]);
                mma_bf16(oc[2*ng],   pl, &vh[ng][0]);
                mma_bf16(oc[2*ng+1], pl, &vh[ng][2]);
            }
        }
        __syncthreads();
    }

    // Epilogue: normalize, store context [b, s, h*64+d]
    float inva = 1.f / l_a, invb = 1.f / l_b;
    int ra = qb*128 + wid*16 + (lane >> 2);
    size_t baseA = (size_t)(b*S_ + ra) * D_ + h*DH_;
    size_t baseB = baseA + (size_t)8 * D_;
    #pragma unroll
    for (int t = 0; t < 8; t++) {
        int d = t*8 + ((lane & 3) << 1);
        *(float2*)&g_C[baseA + d] = make_float2(oc[t][0]*inva, oc[t][1]*inva);
        *(float2*)&g_C[baseB + d] = make_float2(oc[t][2]*invb, oc[t][3]*invb);
    }
}

// ===========================================================================
extern "C" void kernel_launch(void* const* d_in, const int* in_sizes, int n_in,
                              void* d_out, int out_size)
{
    const float* q  = (const float*)d_in[0];
    const float* k  = (const float*)d_in[1];
    const float* v  = (const float*)d_in[2];
    const float* Wq = (const float*)d_in[3];
    const float* bq = (const float*)d_in[4];
    const float* Wk = (const float*)d_in[5];
    const float* bk = (const float*)d_in[6];
    const float* Wv = (const float*)d_in[7];
    const float* bv = (const float*)d_in[8];
    const float* Wo = (const float*)d_in[9];
    const float* bo = (const float*)d_in[10];
    float* out = (float*)d_out;

    float *Qp, *Kp, *Vp, *Cp;
    cudaGetSymbolAddress((void**)&Qp, g_Q);
    cudaGetSymbolAddress((void**)&Kp, g_K);
    cudaGetSymbolAddress((void**)&Vp, g_V);
    cudaGetSymbolAddress((void**)&Cp, g_C);
    __nv_bfloat16 *Xhi, *Xlo, *Whi, *Wlo;
    cudaGetSymbolAddress((void**)&Xhi, g_Xhi);
    cudaGetSymbolAddress((void**)&Xlo, g_Xlo);
    cudaGetSymbolAddress((void**)&Whi, g_Whi);
    cudaGetSymbolAddress((void**)&Wlo, g_Wlo);

    const int gsmem = 2 * 65536;
    cudaFuncSetAttribute(gemm_mma_kernel, cudaFuncAttributeMaxDynamicSharedMemorySize, gsmem);
    dim3 gt(D_/128, MTOT/128);
    const int NXB = (MTOT*D_/4)/256;
    const int NWB = (D_*D_/4)/256;

    split_kernel<<<NXB, 256>>>(q, Xhi, Xlo);
    split_kernel<<<NWB, 256>>>(Wq, Whi, Wlo);
    gemm_mma_kernel<<<gt, 256, gsmem>>>(Xhi, Xlo, Whi, Wlo, bq, Qp);

    split_kernel<<<NXB, 256>>>(k, Xhi, Xlo);
    split_kernel<<<NWB, 256>>>(Wk, Whi, Wlo);
    gemm_mma_kernel<<<gt, 256, gsmem>>>(Xhi, Xlo, Whi, Wlo, bk, Kp);

    split_kernel<<<NXB, 256>>>(v, Xhi, Xlo);
    split_kernel<<<NWB, 256>>>(Wv, Whi, Wlo);
    gemm_mma_kernel<<<gt, 256, gsmem>>>(Xhi, Xlo, Whi, Wlo, bv, Vp);

    rope_kernel<<<(B_*S_*H_*32)/256, 256>>>();
    vtrans_kernel<<<dim3(S_/64, B_*H_), 256>>>();

    const int asmem = 65536;
    cudaFuncSetAttribute(attn_mma_kernel, cudaFuncAttributeMaxDynamicSharedMemorySize, asmem);
    attn_mma_kernel<<<dim3(S_/128, B_*H_), 256, asmem>>>();

    split_kernel<<<NXB, 256>>>(Cp, Xhi, Xlo);
    split_kernel<<<NWB, 256>>>(Wo, Whi, Wlo);
    gemm_mma_kernel<<<gt, 256, gsmem>>>(Xhi, Xlo, Whi, Wlo, bo, out);
}

// round 6
// speedup vs baseline: 3.4670x; 1.2544x over previous
#include <cuda_runtime.h>
#include <cuda_bf16.h>
#include <math.h>
#include <stdint.h>

#define B_  2
#define S_  2048
#define D_  1024
#define H_  16
#define DH_ 64
#define MTOT (B_*S_)   // 4096

__device__ float g_Q[MTOT*D_];
__device__ float g_K[MTOT*D_];
__device__ float g_V[MTOT*D_];
__device__ __nv_bfloat16 g_Xhi[MTOT*D_];
__device__ __nv_bfloat16 g_Xlo[MTOT*D_];
__device__ __nv_bfloat16 g_Whi[D_*D_];
__device__ __nv_bfloat16 g_Wlo[D_*D_];
__device__ __nv_bfloat16 g_Qhi[MTOT*D_];
__device__ __nv_bfloat16 g_Qlo[MTOT*D_];
__device__ __nv_bfloat16 g_Khi[MTOT*D_];
__device__ __nv_bfloat16 g_Klo[MTOT*D_];
__device__ __nv_bfloat16 g_Vthi[MTOT*D_];   // [bh][d][s]
__device__ __nv_bfloat16 g_Vtlo[MTOT*D_];

#define SW128(o) ((o) ^ (((o) >> 3) & 0x70))

static __device__ __forceinline__ uint32_t s2u(const void* p) {
    uint32_t a;
    asm("{ .reg .u64 t; cvta.to.shared.u64 t, %1; cvt.u32.u64 %0, t; }" : "=r"(a) : "l"(p));
    return a;
}
static __device__ __forceinline__ void ldm4(uint32_t* r, uint32_t addr) {
    asm volatile("ldmatrix.sync.aligned.m8n8.x4.shared.b16 {%0,%1,%2,%3}, [%4];"
        : "=r"(r[0]), "=r"(r[1]), "=r"(r[2]), "=r"(r[3]) : "r"(addr));
}
static __device__ __forceinline__ void mma_bf16(float* c, const uint32_t* a, const uint32_t* b) {
    asm volatile("mma.sync.aligned.m16n8k16.row.col.f32.bf16.bf16.f32 "
        "{%0,%1,%2,%3}, {%4,%5,%6,%7}, {%8,%9}, {%0,%1,%2,%3};"
        : "+f"(c[0]), "+f"(c[1]), "+f"(c[2]), "+f"(c[3])
        : "r"(a[0]), "r"(a[1]), "r"(a[2]), "r"(a[3]), "r"(b[0]), "r"(b[1]));
}
static __device__ __forceinline__ void splitpk(float x, float y, uint32_t& hi, uint32_t& lo) {
    __nv_bfloat16 hx = __float2bfloat16(x), hy = __float2bfloat16(y);
    float rx = x - __bfloat162float(hx), ry = y - __bfloat162float(hy);
    __nv_bfloat16 lx = __float2bfloat16(rx), ly = __float2bfloat16(ry);
    hi = (uint32_t)__bfloat16_as_ushort(hx) | ((uint32_t)__bfloat16_as_ushort(hy) << 16);
    lo = (uint32_t)__bfloat16_as_ushort(lx) | ((uint32_t)__bfloat16_as_ushort(ly) << 16);
}
static __device__ __forceinline__ void cp16(uint32_t sa, const void* ga) {
    asm volatile("cp.async.cg.shared.global [%0], [%1], 16;" :: "r"(sa), "l"(ga));
}
#define CP_COMMIT() asm volatile("cp.async.commit_group;" ::: "memory")
#define CP_WAIT0()  asm volatile("cp.async.wait_group 0;" ::: "memory")
#define CP_WAIT1()  asm volatile("cp.async.wait_group 1;" ::: "memory")

// ===========================================================================
// fp32 -> bf16 hi/lo split (8 floats per thread)
// ===========================================================================
__global__ __launch_bounds__(256) void split_kernel(
    const float* __restrict__ x, __nv_bfloat16* __restrict__ hi,
    __nv_bfloat16* __restrict__ lo)
{
    int i = blockIdx.x * 256 + threadIdx.x;
    float4 v0 = ((const float4*)x)[2*i];
    float4 v1 = ((const float4*)x)[2*i+1];
    uint4 hv, lv;
    splitpk(v0.x, v0.y, hv.x, lv.x);
    splitpk(v0.z, v0.w, hv.y, lv.y);
    splitpk(v1.x, v1.y, hv.z, lv.z);
    splitpk(v1.z, v1.w, hv.w, lv.w);
    ((uint4*)hi)[i] = hv;
    ((uint4*)lo)[i] = lv;
}

// ===========================================================================
// Split-bf16 mma.sync GEMM: Y = X @ W^T + bias. 128x128 tile, BK=64,
// 3-stage cp.async pipeline (64KB/stage).
// ===========================================================================
__device__ __forceinline__ void load_chunk_async(
    uint32_t sbase, int kc,
    const __nv_bfloat16* __restrict__ Ahi, const __nv_bfloat16* __restrict__ Alo,
    const __nv_bfloat16* __restrict__ Bhi, const __nv_bfloat16* __restrict__ Blo,
    int m0, int n0, int tid)
{
    #pragma unroll
    for (int i = 0; i < 4; i++) {
        int idx = tid + i * 256;
        int row = idx >> 3, c8 = idx & 7;
        uint32_t so = SW128((uint32_t)(row * 128 + c8 * 16));
        size_t ga = (size_t)(m0 + row) * D_ + kc * 64 + c8 * 8;
        size_t gb = (size_t)(n0 + row) * D_ + kc * 64 + c8 * 8;
        cp16(sbase + so,          Ahi + ga);
        cp16(sbase + 16384u + so, Alo + ga);
        cp16(sbase + 32768u + so, Bhi + gb);
        cp16(sbase + 49152u + so, Blo + gb);
    }
}

__global__ __launch_bounds__(256, 1) void gemm_mma_kernel(
    const __nv_bfloat16* __restrict__ Ahi, const __nv_bfloat16* __restrict__ Alo,
    const __nv_bfloat16* __restrict__ Bhi, const __nv_bfloat16* __restrict__ Blo,
    const float* __restrict__ bias, float* __restrict__ Y)
{
    extern __shared__ char smem[];
    const int tid = threadIdx.x;
    const int lane = tid & 31, wid = tid >> 5;
    const int wm = wid & 3;
    const int wn = wid >> 2;
    const int m0 = blockIdx.y * 128, n0 = blockIdx.x * 128;
    const uint32_t sb = s2u(smem);

    const uint32_t swx = (uint32_t)((lane & 7) << 4);
    const int aRowBase = wm * 32 + (lane & 15);
    const uint32_t aKl = (uint32_t)((lane >> 4) << 4);
    const int bRowBase = wn * 64 + ((lane >> 4) << 3) + (lane & 7);
    const uint32_t bKl = (uint32_t)(((lane >> 3) & 1) << 4);

    float acc[2][8][4];
    #pragma unroll
    for (int mt = 0; mt < 2; mt++)
        #pragma unroll
        for (int nt = 0; nt < 8; nt++)
            #pragma unroll
            for (int r = 0; r < 4; r++) acc[mt][nt][r] = 0.f;

    load_chunk_async(sb,           0, Ahi, Alo, Bhi, Blo, m0, n0, tid); CP_COMMIT();
    load_chunk_async(sb + 65536u,  1, Ahi, Alo, Bhi, Blo, m0, n0, tid); CP_COMMIT();

    int st = 0;
    #pragma unroll 1
    for (int kc = 0; kc < 16; kc++) {
        CP_WAIT1();
        __syncthreads();
        if (kc + 2 < 16) {
            int ps = st + 2; if (ps >= 3) ps -= 3;
            load_chunk_async(sb + (uint32_t)ps * 65536u, kc + 2,
                             Ahi, Alo, Bhi, Blo, m0, n0, tid);
        }
        CP_COMMIT();

        const uint32_t bofs = sb + (uint32_t)st * 65536u;
        #pragma unroll
        for (int kk = 0; kk < 4; kk++) {
            const uint32_t kb = (uint32_t)(kk << 5);
            uint32_t ah[2][4], al[2][4];
            #pragma unroll
            for (int mt = 0; mt < 2; mt++) {
                uint32_t rowoff = (uint32_t)(aRowBase + mt * 16) * 128u;
                uint32_t cofs = (kb + aKl) ^ swx;
                ldm4(ah[mt], bofs + rowoff + cofs);
                ldm4(al[mt], bofs + 16384u + rowoff + cofs);
            }
            uint32_t bh[4][4], bl[4][4];
            #pragma unroll
            for (int ng = 0; ng < 4; ng++) {
                uint32_t rowoff = (uint32_t)(bRowBase + ng * 16) * 128u;
                uint32_t cofs = (kb + bKl) ^ swx;
                ldm4(bh[ng], bofs + 32768u + rowoff + cofs);
                ldm4(bl[ng], bofs + 49152u + rowoff + cofs);
            }
            #pragma unroll
            for (int mt = 0; mt < 2; mt++)
                #pragma unroll
                for (int ng = 0; ng < 4; ng++) {
                    mma_bf16(acc[mt][2*ng],   ah[mt], &bh[ng][0]);
                    mma_bf16(acc[mt][2*ng+1], ah[mt], &bh[ng][2]);
                    mma_bf16(acc[mt][2*ng],   ah[mt], &bl[ng][0]);
                    mma_bf16(acc[mt][2*ng+1], ah[mt], &bl[ng][2]);
                    mma_bf16(acc[mt][2*ng],   al[mt], &bh[ng][0]);
                    mma_bf16(acc[mt][2*ng+1], al[mt], &bh[ng][2]);
                }
        }
        if (++st == 3) st = 0;
    }

    #pragma unroll
    for (int mt = 0; mt < 2; mt++) {
        int r0 = m0 + wm * 32 + mt * 16 + (lane >> 2);
        #pragma unroll
        for (int nt = 0; nt < 8; nt++) {
            int c = n0 + wn * 64 + nt * 8 + ((lane & 3) << 1);
            float2 bb = *(const float2*)&bias[c];
            *(float2*)&Y[(size_t)r0 * D_ + c] =
                make_float2(acc[mt][nt][0] + bb.x, acc[mt][nt][1] + bb.y);
            *(float2*)&Y[(size_t)(r0 + 8) * D_ + c] =
                make_float2(acc[mt][nt][2] + bb.x, acc[mt][nt][3] + bb.y);
        }
    }
}

// ===========================================================================
// RoPE: rotates Q,K in fp32, emits bf16 hi/lo splits.
// ===========================================================================
__global__ __launch_bounds__(256) void rope_kernel()
{
    __shared__ float sinv[32];
    if (threadIdx.x < 32) {
        float coef = -(4.0f * logf(10.0f)) / 64.0f;
        float arg  = (float)(2 * threadIdx.x) * coef;
        sinv[threadIdx.x] = (float)exp((double)arg);
    }
    __syncthreads();

    int idx = blockIdx.x * blockDim.x + threadIdx.x;
    int j = idx & 31;
    int t = idx >> 5;
    int h = t & (H_ - 1);
    int rowi = t >> 4;
    int s = rowi & (S_ - 1);

    float ang = (float)s * sinv[j];
    float sn, cs;
    sincosf(ang, &sn, &cs);

    size_t base = (size_t)rowi * D_ + h * DH_ + 2 * j;
    float x1 = g_Q[base], x2 = g_Q[base+1];
    float y1 =  x1 * sn - x2 * cs;
    float y2 = -x1 * cs - x2 * sn;
    uint32_t hi, lo;
    splitpk(y1, y2, hi, lo);
    *(uint32_t*)&g_Qhi[base] = hi;
    *(uint32_t*)&g_Qlo[base] = lo;

    x1 = g_K[base]; x2 = g_K[base+1];
    y1 =  x1 * sn - x2 * cs;
    y2 = -x1 * cs - x2 * sn;
    splitpk(y1, y2, hi, lo);
    *(uint32_t*)&g_Khi[base] = hi;
    *(uint32_t*)&g_Klo[base] = lo;
}

// ===========================================================================
// V transpose + split: g_V [b,s,h,d] -> g_Vt{hi,lo} [bh, d, s]
// ===========================================================================
__global__ __launch_bounds__(256) void vtrans_kernel()
{
    __shared__ float sst[64][65];
    const int tid = threadIdx.x;
    const int st = blockIdx.x, bh = blockIdx.y;
    const int b = bh >> 4, h = bh & 15;

    #pragma unroll
    for (int it = 0; it < 4; it++) {
        int r = it * 16 + (tid >> 4);
        int c = (tid & 15) << 2;
        float4 v = *(const float4*)&g_V[(size_t)(b*S_ + st*64 + r)*D_ + h*DH_ + c];
        sst[r][c+0] = v.x; sst[r][c+1] = v.y; sst[r][c+2] = v.z; sst[r][c+3] = v.w;
    }
    __syncthreads();

    const int d = tid >> 2;
    const int cb = (tid & 3) << 4;
    uint32_t hi[8], lo[8];
    #pragma unroll
    for (int i = 0; i < 8; i++)
        splitpk(sst[cb + 2*i][d], sst[cb + 2*i + 1][d], hi[i], lo[i]);
    size_t ga = (size_t)(bh * 64 + d) * S_ + st * 64 + cb;
    *(uint4*)&g_Vthi[ga]     = make_uint4(hi[0], hi[1], hi[2], hi[3]);
    *(uint4*)&g_Vthi[ga + 8] = make_uint4(hi[4], hi[5], hi[6], hi[7]);
    *(uint4*)&g_Vtlo[ga]     = make_uint4(lo[0], lo[1], lo[2], lo[3]);
    *(uint4*)&g_Vtlo[ga + 8] = make_uint4(lo[4], lo[5], lo[6], lo[7]);
}

// ===========================================================================
// Causal flash attention, split-bf16 mma.sync, 2-stage cp.async K/V.
// smem: Qhi 16K | Qlo 16K | stage0 32K | stage1 32K = 96K
// Epilogue writes bf16 splits of context directly to g_Xhi/g_Xlo.
// ===========================================================================
__device__ __forceinline__ void load_kv_async(uint32_t sstage, int kb,
                                              int b, int bh, int h, int tid)
{
    #pragma unroll
    for (int i = 0; i < 2; i++) {
        int idx = tid + i * 256, row = idx >> 3, c8 = idx & 7;
        uint32_t so = SW128((uint32_t)(row * 128 + c8 * 16));
        size_t gk = (size_t)(b*S_ + kb*64 + row) * D_ + h*DH_ + c8*8;
        size_t gv = (size_t)(bh*64 + row) * S_ + (size_t)kb*64 + c8*8;
        cp16(sstage + so,          g_Khi + gk);
        cp16(sstage + 8192u  + so, g_Klo + gk);
        cp16(sstage + 16384u + so, g_Vthi + gv);
        cp16(sstage + 24576u + so, g_Vtlo + gv);
    }
}

__global__ __launch_bounds__(256, 1) void attn_mma_kernel()
{
    extern __shared__ char smA[];
    const uint32_t QHI = 0, QLO = 16384, STG0 = 32768;
    const uint32_t sb = s2u(smA);
    const int tid = threadIdx.x, lane = tid & 31, wid = tid >> 5;
    const int qb = gridDim.x - 1 - blockIdx.x;
    const int bh = blockIdx.y, b = bh >> 4, h = bh & 15;

    // Load Q tile (hi+lo)
    #pragma unroll
    for (int i = 0; i < 4; i++) {
        int idx = tid + i * 256, row = idx >> 3, c8 = idx & 7;
        uint32_t so = SW128((uint32_t)(row * 128 + c8 * 16));
        size_t ga = (size_t)(b*S_ + qb*128 + row) * D_ + h*DH_ + c8*8;
        *(uint4*)(smA + QHI + so) = *(const uint4*)(g_Qhi + ga);
        *(uint4*)(smA + QLO + so) = *(const uint4*)(g_Qlo + ga);
    }
    load_kv_async(sb + STG0, 0, b, bh, h, tid);
    CP_COMMIT();
    __syncthreads();

    const uint32_t swx  = (uint32_t)((lane & 7) << 4);
    const uint32_t aRow = (uint32_t)(wid * 16 + (lane & 15));
    const uint32_t aKl  = (uint32_t)((lane >> 4) << 4);
    const uint32_t bRow = (uint32_t)(((lane >> 4) << 3) + (lane & 7));
    const uint32_t bKl  = (uint32_t)(((lane >> 3) & 1) << 4);

    uint32_t qh[4][4], ql[4][4];
    #pragma unroll
    for (int kk = 0; kk < 4; kk++) {
        uint32_t cofs = ((uint32_t)(kk << 5) + aKl) ^ swx;
        ldm4(qh[kk], sb + QHI + aRow * 128u + cofs);
        ldm4(ql[kk], sb + QLO + aRow * 128u + cofs);
    }

    float m_a = -1e30f, m_b = -1e30f, l_a = 0.f, l_b = 0.f;
    float oc[8][4];
    #pragma unroll
    for (int t = 0; t < 8; t++)
        #pragma unroll
        for (int r = 0; r < 4; r++) oc[t][r] = 0.f;

    const int nkb = 2 * qb + 2;
    #pragma unroll 1
    for (int kb = 0; kb < nkb; kb++) {
        CP_WAIT0();
        __syncthreads();
        const uint32_t sst = sb + STG0 + (uint32_t)(kb & 1) * 32768u;
        if (kb + 1 < nkb)
            load_kv_async(sb + STG0 + (uint32_t)((kb + 1) & 1) * 32768u,
                          kb + 1, b, bh, h, tid);
        CP_COMMIT();

        // S = Q K^T (3-term split)
        float sc[8][4];
        #pragma unroll
        for (int t = 0; t < 8; t++)
            #pragma unroll
            for (int r = 0; r < 4; r++) sc[t][r] = 0.f;
        #pragma unroll
        for (int kk = 0; kk < 4; kk++) {
            uint32_t kh[4][4], kl[4][4];
            uint32_t cofs = ((uint32_t)(kk << 5) + bKl) ^ swx;
            #pragma unroll
            for (int ng = 0; ng < 4; ng++) {
                uint32_t ro = (bRow + (uint32_t)(ng * 16)) * 128u;
                ldm4(kh[ng], sst + ro + cofs);
                ldm4(kl[ng], sst + 8192u + ro + cofs);
            }
            #pragma unroll
            for (int ng = 0; ng < 4; ng++) {
                mma_bf16(sc[2*ng],   qh[kk], &kh[ng][0]);
                mma_bf16(sc[2*ng+1], qh[kk], &kh[ng][2]);
                mma_bf16(sc[2*ng],   qh[kk], &kl[ng][0]);
                mma_bf16(sc[2*ng+1], qh[kk], &kl[ng][2]);
                mma_bf16(sc[2*ng],   ql[kk], &kh[ng][0]);
                mma_bf16(sc[2*ng+1], ql[kk], &kh[ng][2]);
            }
        }

        const int rga = qb*128 + wid*16 + (lane >> 2);
        if (kb >= 2*qb) {
            #pragma unroll
            for (int t = 0; t < 8; t++) {
                int cg = kb*64 + t*8 + ((lane & 3) << 1);
                if (cg     > rga)     sc[t][0] = -1e30f;
                if (cg + 1 > rga)     sc[t][1] = -1e30f;
                if (cg     > rga + 8) sc[t][2] = -1e30f;
                if (cg + 1 > rga + 8) sc[t][3] = -1e30f;
            }
        }

        // Online softmax
        float mxa = -1e30f, mxb = -1e30f;
        #pragma unroll
        for (int t = 0; t < 8; t++) {
            mxa = fmaxf(mxa, fmaxf(sc[t][0], sc[t][1]));
            mxb = fmaxf(mxb, fmaxf(sc[t][2], sc[t][3]));
        }
        mxa = fmaxf(mxa, __shfl_xor_sync(0xffffffffu, mxa, 1));
        mxa = fmaxf(mxa, __shfl_xor_sync(0xffffffffu, mxa, 2));
        mxb = fmaxf(mxb, __shfl_xor_sync(0xffffffffu, mxb, 1));
        mxb = fmaxf(mxb, __shfl_xor_sync(0xffffffffu, mxb, 2));
        float mna = fmaxf(m_a, mxa), mnb = fmaxf(m_b, mxb);
        float alpa = __expf(m_a - mna), alpb = __expf(m_b - mnb);
        float psa = 0.f, psb = 0.f;
        #pragma unroll
        for (int t = 0; t < 8; t++) {
            sc[t][0] = __expf(sc[t][0] - mna); psa += sc[t][0];
            sc[t][1] = __expf(sc[t][1] - mna); psa += sc[t][1];
            sc[t][2] = __expf(sc[t][2] - mnb); psb += sc[t][2];
            sc[t][3] = __expf(sc[t][3] - mnb); psb += sc[t][3];
        }
        psa += __shfl_xor_sync(0xffffffffu, psa, 1);
        psa += __shfl_xor_sync(0xffffffffu, psa, 2);
        psb += __shfl_xor_sync(0xffffffffu, psb, 1);
        psb += __shfl_xor_sync(0xffffffffu, psb, 2);
        l_a = l_a * alpa + psa;  m_a = mna;
        l_b = l_b * alpb + psb;  m_b = mnb;
        #pragma unroll
        for (int t = 0; t < 8; t++) {
            oc[t][0] *= alpa; oc[t][1] *= alpa;
            oc[t][2] *= alpb; oc[t][3] *= alpb;
        }

        // O += P V
        #pragma unroll
        for (int kk = 0; kk < 4; kk++) {
            uint32_t ph[4], pl[4];
            splitpk(sc[2*kk][0],   sc[2*kk][1],   ph[0], pl[0]);
            splitpk(sc[2*kk][2],   sc[2*kk][3],   ph[1], pl[1]);
            splitpk(sc[2*kk+1][0], sc[2*kk+1][1], ph[2], pl[2]);
            splitpk(sc[2*kk+1][2], sc[2*kk+1][3], ph[3], pl[3]);
            uint32_t vh[4][4], vl[4][4];
            uint32_t cofs = ((uint32_t)(kk << 5) + bKl) ^ swx;
            #pragma unroll
            for (int ng = 0; ng < 4; ng++) {
                uint32_t ro = (bRow + (uint32_t)(ng * 16)) * 128u;
                ldm4(vh[ng], sst + 16384u + ro + cofs);
                ldm4(vl[ng], sst + 24576u + ro + cofs);
            }
            #pragma unroll
            for (int ng = 0; ng < 4; ng++) {
                mma_bf16(oc[2*ng],   ph, &vh[ng][0]);
                mma_bf16(oc[2*ng+1], ph, &vh[ng][2]);
                mma_bf16(oc[2*ng],   ph, &vl[ng][0]);
                mma_bf16(oc[2*ng+1], ph, &vl[ng][2]);
                mma_bf16(oc[2*ng],   pl, &vh[ng][0]);
                mma_bf16(oc[2*ng+1], pl, &vh[ng][2]);
            }
        }
    }

    // Epilogue: normalize + split directly into g_Xhi/g_Xlo
    float inva = 1.f / l_a, invb = 1.f / l_b;
    int ra = qb*128 + wid*16 + (lane >> 2);
    size_t baseA = (size_t)(b*S_ + ra) * D_ + h*DH_;
    size_t baseB = baseA + (size_t)8 * D_;
    #pragma unroll
    for (int t = 0; t < 8; t++) {
        int d = t*8 + ((lane & 3) << 1);
        uint32_t hi, lo;
        splitpk(oc[t][0]*inva, oc[t][1]*inva, hi, lo);
        *(uint32_t*)&g_Xhi[baseA + d] = hi;
        *(uint32_t*)&g_Xlo[baseA + d] = lo;
        splitpk(oc[t][2]*invb, oc[t][3]*invb, hi, lo);
        *(uint32_t*)&g_Xhi[baseB + d] = hi;
        *(uint32_t*)&g_Xlo[baseB + d] = lo;
    }
}

// ===========================================================================
extern "C" void kernel_launch(void* const* d_in, const int* in_sizes, int n_in,
                              void* d_out, int out_size)
{
    const float* q  = (const float*)d_in[0];
    const float* k  = (const float*)d_in[1];
    const float* v  = (const float*)d_in[2];
    const float* Wq = (const float*)d_in[3];
    const float* bq = (const float*)d_in[4];
    const float* Wk = (const float*)d_in[5];
    const float* bk = (const float*)d_in[6];
    const float* Wv = (const float*)d_in[7];
    const float* bv = (const float*)d_in[8];
    const float* Wo = (const float*)d_in[9];
    const float* bo = (const float*)d_in[10];
    float* out = (float*)d_out;

    float *Qp, *Kp, *Vp;
    cudaGetSymbolAddress((void**)&Qp, g_Q);
    cudaGetSymbolAddress((void**)&Kp, g_K);
    cudaGetSymbolAddress((void**)&Vp, g_V);
    __nv_bfloat16 *Xhi, *Xlo, *Whi, *Wlo;
    cudaGetSymbolAddress((void**)&Xhi, g_Xhi);
    cudaGetSymbolAddress((void**)&Xlo, g_Xlo);
    cudaGetSymbolAddress((void**)&Whi, g_Whi);
    cudaGetSymbolAddress((void**)&Wlo, g_Wlo);

    const int gsmem = 3 * 65536;  // 196608
    cudaFuncSetAttribute(gemm_mma_kernel, cudaFuncAttributeMaxDynamicSharedMemorySize, gsmem);
    dim3 gt(D_/128, MTOT/128);
    const int NXB = (MTOT*D_/8)/256;   // 2048
    const int NWB = (D_*D_/8)/256;     // 512

    split_kernel<<<NXB, 256>>>(q, Xhi, Xlo);
    split_kernel<<<NWB, 256>>>(Wq, Whi, Wlo);
    gemm_mma_kernel<<<gt, 256, gsmem>>>(Xhi, Xlo, Whi, Wlo, bq, Qp);

    split_kernel<<<NXB, 256>>>(k, Xhi, Xlo);
    split_kernel<<<NWB, 256>>>(Wk, Whi, Wlo);
    gemm_mma_kernel<<<gt, 256, gsmem>>>(Xhi, Xlo, Whi, Wlo, bk, Kp);

    split_kernel<<<NXB, 256>>>(v, Xhi, Xlo);
    split_kernel<<<NWB, 256>>>(Wv, Whi, Wlo);
    gemm_mma_kernel<<<gt, 256, gsmem>>>(Xhi, Xlo, Whi, Wlo, bv, Vp);

    rope_kernel<<<(B_*S_*H_*32)/256, 256>>>();
    vtrans_kernel<<<dim3(S_/64, B_*H_), 256>>>();

    const int asmem = 32768 + 2 * 32768;  // 98304
    cudaFuncSetAttribute(attn_mma_kernel, cudaFuncAttributeMaxDynamicSharedMemorySize, asmem);
    attn_mma_kernel<<<dim3(S_/128, B_*H_), 256, asmem>>>();

    split_kernel<<<NWB, 256>>>(Wo, Whi, Wlo);
    gemm_mma_kernel<<<gt, 256, gsmem>>>(Xhi, Xlo, Whi, Wlo, bo, out);
}

// round 7
// speedup vs baseline: 3.5255x; 1.0169x over previous
#include <cuda_runtime.h>
#include <cuda_bf16.h>
#include <math.h>
#include <stdint.h>

#define B_  2
#define S_  2048
#define D_  1024
#define H_  16
#define DH_ 64
#define MTOT (B_*S_)   // 4096
#define MD_ ((size_t)MTOT*D_)
#define DD_ ((size_t)D_*D_)

__device__ float g_V[MTOT*D_];
__device__ __nv_bfloat16 g_Xhi3[3*MTOT*D_];
__device__ __nv_bfloat16 g_Xlo3[3*MTOT*D_];
__device__ __nv_bfloat16 g_Whi4[4*D_*D_];
__device__ __nv_bfloat16 g_Wlo4[4*D_*D_];
__device__ __nv_bfloat16 g_Qhi[MTOT*D_];
__device__ __nv_bfloat16 g_Qlo[MTOT*D_];
__device__ __nv_bfloat16 g_Khi[MTOT*D_];
__device__ __nv_bfloat16 g_Klo[MTOT*D_];
__device__ __nv_bfloat16 g_Vthi[MTOT*D_];   // [bh][d][s]
__device__ __nv_bfloat16 g_Vtlo[MTOT*D_];
__device__ __nv_bfloat16 g_Chi[MTOT*D_];
__device__ __nv_bfloat16 g_Clo[MTOT*D_];

#define SW128(o) ((o) ^ (((o) >> 3) & 0x70))

static __device__ __forceinline__ uint32_t s2u(const void* p) {
    uint32_t a;
    asm("{ .reg .u64 t; cvta.to.shared.u64 t, %1; cvt.u32.u64 %0, t; }" : "=r"(a) : "l"(p));
    return a;
}
static __device__ __forceinline__ void ldm4(uint32_t* r, uint32_t addr) {
    asm volatile("ldmatrix.sync.aligned.m8n8.x4.shared.b16 {%0,%1,%2,%3}, [%4];"
        : "=r"(r[0]), "=r"(r[1]), "=r"(r[2]), "=r"(r[3]) : "r"(addr));
}
static __device__ __forceinline__ void mma_bf16(float* c, const uint32_t* a, const uint32_t* b) {
    asm volatile("mma.sync.aligned.m16n8k16.row.col.f32.bf16.bf16.f32 "
        "{%0,%1,%2,%3}, {%4,%5,%6,%7}, {%8,%9}, {%0,%1,%2,%3};"
        : "+f"(c[0]), "+f"(c[1]), "+f"(c[2]), "+f"(c[3])
        : "r"(a[0]), "r"(a[1]), "r"(a[2]), "r"(a[3]), "r"(b[0]), "r"(b[1]));
}
static __device__ __forceinline__ void splitpk(float x, float y, uint32_t& hi, uint32_t& lo) {
    __nv_bfloat16 hx = __float2bfloat16(x), hy = __float2bfloat16(y);
    float rx = x - __bfloat162float(hx), ry = y - __bfloat162float(hy);
    __nv_bfloat16 lx = __float2bfloat16(rx), ly = __float2bfloat16(ry);
    hi = (uint32_t)__bfloat16_as_ushort(hx) | ((uint32_t)__bfloat16_as_ushort(hy) << 16);
    lo = (uint32_t)__bfloat16_as_ushort(lx) | ((uint32_t)__bfloat16_as_ushort(ly) << 16);
}
static __device__ __forceinline__ void cp16(uint32_t sa, const void* ga) {
    asm volatile("cp.async.cg.shared.global [%0], [%1], 16;" :: "r"(sa), "l"(ga));
}
#define CP_COMMIT() asm volatile("cp.async.commit_group;" ::: "memory")
#define CP_WAIT0()  asm volatile("cp.async.wait_group 0;" ::: "memory")
#define CP_WAIT1()  asm volatile("cp.async.wait_group 1;" ::: "memory")

// ===========================================================================
// Batched fp32 -> bf16 hi/lo splits
// ===========================================================================
__global__ __launch_bounds__(256) void splitx_kernel(
    const float* __restrict__ q, const float* __restrict__ k,
    const float* __restrict__ v)
{
    const int z = blockIdx.z;
    const float* x = (z == 0) ? q : (z == 1) ? k : v;
    size_t off = (size_t)z * MD_;
    int i = blockIdx.x * 256 + threadIdx.x;
    float4 v0 = ((const float4*)x)[2*i];
    float4 v1 = ((const float4*)x)[2*i+1];
    uint4 hv, lv;
    splitpk(v0.x, v0.y, hv.x, lv.x);
    splitpk(v0.z, v0.w, hv.y, lv.y);
    splitpk(v1.x, v1.y, hv.z, lv.z);
    splitpk(v1.z, v1.w, hv.w, lv.w);
    ((uint4*)(g_Xhi3 + off))[i] = hv;
    ((uint4*)(g_Xlo3 + off))[i] = lv;
}

__global__ __launch_bounds__(256) void splitw_kernel(
    const float* __restrict__ wq, const float* __restrict__ wk,
    const float* __restrict__ wv, const float* __restrict__ wo)
{
    const int z = blockIdx.z;
    const float* x = (z == 0) ? wq : (z == 1) ? wk : (z == 2) ? wv : wo;
    size_t off = (size_t)z * DD_;
    int i = blockIdx.x * 256 + threadIdx.x;
    float4 v0 = ((const float4*)x)[2*i];
    float4 v1 = ((const float4*)x)[2*i+1];
    uint4 hv, lv;
    splitpk(v0.x, v0.y, hv.x, lv.x);
    splitpk(v0.z, v0.w, hv.y, lv.y);
    splitpk(v1.x, v1.y, hv.z, lv.z);
    splitpk(v1.z, v1.w, hv.w, lv.w);
    ((uint4*)(g_Whi4 + off))[i] = hv;
    ((uint4*)(g_Wlo4 + off))[i] = lv;
}

// ===========================================================================
// GEMM mainloop (shared): 128x128 tile, BK=64, 3-stage cp.async.
// ===========================================================================
__device__ __forceinline__ void load_chunk_async(
    uint32_t sbase, int kc,
    const __nv_bfloat16* Ahi, const __nv_bfloat16* Alo,
    const __nv_bfloat16* Bhi, const __nv_bfloat16* Blo,
    int m0, int n0, int tid)
{
    #pragma unroll
    for (int i = 0; i < 4; i++) {
        int idx = tid + i * 256;
        int row = idx >> 3, c8 = idx & 7;
        uint32_t so = SW128((uint32_t)(row * 128 + c8 * 16));
        size_t ga = (size_t)(m0 + row) * D_ + kc * 64 + c8 * 8;
        size_t gb = (size_t)(n0 + row) * D_ + kc * 64 + c8 * 8;
        cp16(sbase + so,          Ahi + ga);
        cp16(sbase + 16384u + so, Alo + ga);
        cp16(sbase + 32768u + so, Bhi + gb);
        cp16(sbase + 49152u + so, Blo + gb);
    }
}

__device__ __forceinline__ void gemm_mainloop(
    uint32_t sb, const __nv_bfloat16* Ahi, const __nv_bfloat16* Alo,
    const __nv_bfloat16* Bhi, const __nv_bfloat16* Blo,
    int m0, int n0, int tid, int lane, int wm, int wn,
    float acc[2][8][4])
{
    const uint32_t swx = (uint32_t)((lane & 7) << 4);
    const int aRowBase = wm * 32 + (lane & 15);
    const uint32_t aKl = (uint32_t)((lane >> 4) << 4);
    const int bRowBase = wn * 64 + ((lane >> 4) << 3) + (lane & 7);
    const uint32_t bKl = (uint32_t)(((lane >> 3) & 1) << 4);

    load_chunk_async(sb,          0, Ahi, Alo, Bhi, Blo, m0, n0, tid); CP_COMMIT();
    load_chunk_async(sb + 65536u, 1, Ahi, Alo, Bhi, Blo, m0, n0, tid); CP_COMMIT();

    int st = 0;
    #pragma unroll 1
    for (int kc = 0; kc < 16; kc++) {
        CP_WAIT1();
        __syncthreads();
        if (kc + 2 < 16) {
            int ps = st + 2; if (ps >= 3) ps -= 3;
            load_chunk_async(sb + (uint32_t)ps * 65536u, kc + 2,
                             Ahi, Alo, Bhi, Blo, m0, n0, tid);
        }
        CP_COMMIT();

        const uint32_t bofs = sb + (uint32_t)st * 65536u;
        #pragma unroll
        for (int kk = 0; kk < 4; kk++) {
            const uint32_t kb = (uint32_t)(kk << 5);
            uint32_t ah[2][4], al[2][4];
            #pragma unroll
            for (int mt = 0; mt < 2; mt++) {
                uint32_t rowoff = (uint32_t)(aRowBase + mt * 16) * 128u;
                uint32_t cofs = (kb + aKl) ^ swx;
                ldm4(ah[mt], bofs + rowoff + cofs);
                ldm4(al[mt], bofs + 16384u + rowoff + cofs);
            }
            uint32_t bh[4][4], bl[4][4];
            #pragma unroll
            for (int ng = 0; ng < 4; ng++) {
                uint32_t rowoff = (uint32_t)(bRowBase + ng * 16) * 128u;
                uint32_t cofs = (kb + bKl) ^ swx;
                ldm4(bh[ng], bofs + 32768u + rowoff + cofs);
                ldm4(bl[ng], bofs + 49152u + rowoff + cofs);
            }
            #pragma unroll
            for (int mt = 0; mt < 2; mt++)
                #pragma unroll
                for (int ng = 0; ng < 4; ng++) {
                    mma_bf16(acc[mt][2*ng],   ah[mt], &bh[ng][0]);
                    mma_bf16(acc[mt][2*ng+1], ah[mt], &bh[ng][2]);
                    mma_bf16(acc[mt][2*ng],   ah[mt], &bl[ng][0]);
                    mma_bf16(acc[mt][2*ng+1], ah[mt], &bl[ng][2]);
                    mma_bf16(acc[mt][2*ng],   al[mt], &bh[ng][0]);
                    mma_bf16(acc[mt][2*ng+1], al[mt], &bh[ng][2]);
                }
        }
        if (++st == 3) st = 0;
    }
}

// ===========================================================================
// Fused QKV projection: grid.z selects (X, W, bias, epilogue).
// z=0 (Q), z=1 (K): rope + bf16 split epilogue. z=2 (V): fp32 store.
// ===========================================================================
__global__ __launch_bounds__(256, 1) void gemm_qkv_kernel(
    const float* __restrict__ bq, const float* __restrict__ bk,
    const float* __restrict__ bv)
{
    extern __shared__ char smem[];
    __shared__ float sinv[32];
    const int tid = threadIdx.x, lane = tid & 31, wid = tid >> 5;
    const int wm = wid & 3, wn = wid >> 2;
    const int z = blockIdx.z;
    const int m0 = blockIdx.y * 128, n0 = blockIdx.x * 128;
    const uint32_t sb = s2u(smem);

    if (tid < 32) {
        float coef = -(4.0f * logf(10.0f)) / 64.0f;
        float arg  = (float)(2 * tid) * coef;
        sinv[tid] = (float)exp((double)arg);
    }

    const __nv_bfloat16* Ahi = g_Xhi3 + (size_t)z * MD_;
    const __nv_bfloat16* Alo = g_Xlo3 + (size_t)z * MD_;
    const __nv_bfloat16* Bhi = g_Whi4 + (size_t)z * DD_;
    const __nv_bfloat16* Blo = g_Wlo4 + (size_t)z * DD_;
    const float* bias = (z == 0) ? bq : (z == 1) ? bk : bv;

    float acc[2][8][4];
    #pragma unroll
    for (int mt = 0; mt < 2; mt++)
        #pragma unroll
        for (int nt = 0; nt < 8; nt++)
            #pragma unroll
            for (int r = 0; r < 4; r++) acc[mt][nt][r] = 0.f;

    gemm_mainloop(sb, Ahi, Alo, Bhi, Blo, m0, n0, tid, lane, wm, wn, acc);

    if (z == 2) {
        #pragma unroll
        for (int mt = 0; mt < 2; mt++) {
            int r0 = m0 + wm * 32 + mt * 16 + (lane >> 2);
            #pragma unroll
            for (int nt = 0; nt < 8; nt++) {
                int c = n0 + wn * 64 + nt * 8 + ((lane & 3) << 1);
                float2 bb = *(const float2*)&bias[c];
                *(float2*)&g_V[(size_t)r0 * D_ + c] =
                    make_float2(acc[mt][nt][0] + bb.x, acc[mt][nt][1] + bb.y);
                *(float2*)&g_V[(size_t)(r0 + 8) * D_ + c] =
                    make_float2(acc[mt][nt][2] + bb.x, acc[mt][nt][3] + bb.y);
            }
        }
    } else {
        __nv_bfloat16* dhi = z ? g_Khi : g_Qhi;
        __nv_bfloat16* dlo = z ? g_Klo : g_Qlo;
        #pragma unroll
        for (int mt = 0; mt < 2; mt++) {
            int r0 = m0 + wm * 32 + mt * 16 + (lane >> 2);
            #pragma unroll
            for (int nt = 0; nt < 8; nt++) {
                int c = n0 + wn * 64 + nt * 8 + ((lane & 3) << 1);
                float2 bb = *(const float2*)&bias[c];
                float inv = sinv[(c & 63) >> 1];
                uint32_t hi, lo;
                // row r0
                {
                    int s = r0 & (S_ - 1);
                    float sn, cs;
                    sincosf((float)s * inv, &sn, &cs);
                    float x1 = acc[mt][nt][0] + bb.x;
                    float x2 = acc[mt][nt][1] + bb.y;
                    splitpk(x1 * sn - x2 * cs, -x1 * cs - x2 * sn, hi, lo);
                    *(uint32_t*)&dhi[(size_t)r0 * D_ + c] = hi;
                    *(uint32_t*)&dlo[(size_t)r0 * D_ + c] = lo;
                }
                // row r0+8
                {
                    int s = (r0 + 8) & (S_ - 1);
                    float sn, cs;
                    sincosf((float)s * inv, &sn, &cs);
                    float x1 = acc[mt][nt][2] + bb.x;
                    float x2 = acc[mt][nt][3] + bb.y;
                    splitpk(x1 * sn - x2 * cs, -x1 * cs - x2 * sn, hi, lo);
                    *(uint32_t*)&dhi[(size_t)(r0 + 8) * D_ + c] = hi;
                    *(uint32_t*)&dlo[(size_t)(r0 + 8) * D_ + c] = lo;
                }
            }
        }
    }
}

// ===========================================================================
// Output projection: C (split) @ Wo^T + bo -> fp32 out
// ===========================================================================
__global__ __launch_bounds__(256, 1) void gemm_o_kernel(
    const float* __restrict__ bias, float* __restrict__ Y)
{
    extern __shared__ char smem[];
    const int tid = threadIdx.x, lane = tid & 31, wid = tid >> 5;
    const int wm = wid & 3, wn = wid >> 2;
    const int m0 = blockIdx.y * 128, n0 = blockIdx.x * 128;
    const uint32_t sb = s2u(smem);

    float acc[2][8][4];
    #pragma unroll
    for (int mt = 0; mt < 2; mt++)
        #pragma unroll
        for (int nt = 0; nt < 8; nt++)
            #pragma unroll
            for (int r = 0; r < 4; r++) acc[mt][nt][r] = 0.f;

    gemm_mainloop(sb, g_Chi, g_Clo, g_Whi4 + 3 * DD_, g_Wlo4 + 3 * DD_,
                  m0, n0, tid, lane, wm, wn, acc);

    #pragma unroll
    for (int mt = 0; mt < 2; mt++) {
        int r0 = m0 + wm * 32 + mt * 16 + (lane >> 2);
        #pragma unroll
        for (int nt = 0; nt < 8; nt++) {
            int c = n0 + wn * 64 + nt * 8 + ((lane & 3) << 1);
            float2 bb = *(const float2*)&bias[c];
            *(float2*)&Y[(size_t)r0 * D_ + c] =
                make_float2(acc[mt][nt][0] + bb.x, acc[mt][nt][1] + bb.y);
            *(float2*)&Y[(size_t)(r0 + 8) * D_ + c] =
                make_float2(acc[mt][nt][2] + bb.x, acc[mt][nt][3] + bb.y);
        }
    }
}

// ===========================================================================
// V transpose + split: g_V [b,s,h,d] -> g_Vt{hi,lo} [bh, d, s]
// ===========================================================================
__global__ __launch_bounds__(256) void vtrans_kernel()
{
    __shared__ float sst[64][65];
    const int tid = threadIdx.x;
    const int st = blockIdx.x, bh = blockIdx.y;
    const int b = bh >> 4, h = bh & 15;

    #pragma unroll
    for (int it = 0; it < 4; it++) {
        int r = it * 16 + (tid >> 4);
        int c = (tid & 15) << 2;
        float4 v = *(const float4*)&g_V[(size_t)(b*S_ + st*64 + r)*D_ + h*DH_ + c];
        sst[r][c+0] = v.x; sst[r][c+1] = v.y; sst[r][c+2] = v.z; sst[r][c+3] = v.w;
    }
    __syncthreads();

    const int d = tid >> 2;
    const int cb = (tid & 3) << 4;
    uint32_t hi[8], lo[8];
    #pragma unroll
    for (int i = 0; i < 8; i++)
        splitpk(sst[cb + 2*i][d], sst[cb + 2*i + 1][d], hi[i], lo[i]);
    size_t ga = (size_t)(bh * 64 + d) * S_ + st * 64 + cb;
    *(uint4*)&g_Vthi[ga]     = make_uint4(hi[0], hi[1], hi[2], hi[3]);
    *(uint4*)&g_Vthi[ga + 8] = make_uint4(hi[4], hi[5], hi[6], hi[7]);
    *(uint4*)&g_Vtlo[ga]     = make_uint4(lo[0], lo[1], lo[2], lo[3]);
    *(uint4*)&g_Vtlo[ga + 8] = make_uint4(lo[4], lo[5], lo[6], lo[7]);
}

// ===========================================================================
// Causal flash attention, split-bf16 mma.sync, 2-stage cp.async K/V.
// ===========================================================================
__device__ __forceinline__ void load_kv_async(uint32_t sstage, int kb,
                                              int b, int bh, int h, int tid)
{
    #pragma unroll
    for (int i = 0; i < 2; i++) {
        int idx = tid + i * 256, row = idx >> 3, c8 = idx & 7;
        uint32_t so = SW128((uint32_t)(row * 128 + c8 * 16));
        size_t gk = (size_t)(b*S_ + kb*64 + row) * D_ + h*DH_ + c8*8;
        size_t gv = (size_t)(bh*64 + row) * S_ + (size_t)kb*64 + c8*8;
        cp16(sstage + so,          g_Khi + gk);
        cp16(sstage + 8192u  + so, g_Klo + gk);
        cp16(sstage + 16384u + so, g_Vthi + gv);
        cp16(sstage + 24576u + so, g_Vtlo + gv);
    }
}

__global__ __launch_bounds__(256, 1) void attn_mma_kernel()
{
    extern __shared__ char smA[];
    const uint32_t QHI = 0, QLO = 16384, STG0 = 32768;
    const uint32_t sb = s2u(smA);
    const int tid = threadIdx.x, lane = tid & 31, wid = tid >> 5;
    const int qb = gridDim.x - 1 - blockIdx.x;
    const int bh = blockIdx.y, b = bh >> 4, h = bh & 15;

    #pragma unroll
    for (int i = 0; i < 4; i++) {
        int idx = tid + i * 256, row = idx >> 3, c8 = idx & 7;
        uint32_t so = SW128((uint32_t)(row * 128 + c8 * 16));
        size_t ga = (size_t)(b*S_ + qb*128 + row) * D_ + h*DH_ + c8*8;
        *(uint4*)(smA + QHI + so) = *(const uint4*)(g_Qhi + ga);
        *(uint4*)(smA + QLO + so) = *(const uint4*)(g_Qlo + ga);
    }
    load_kv_async(sb + STG0, 0, b, bh, h, tid);
    CP_COMMIT();
    __syncthreads();

    const uint32_t swx  = (uint32_t)((lane & 7) << 4);
    const uint32_t aRow = (uint32_t)(wid * 16 + (lane & 15));
    const uint32_t aKl  = (uint32_t)((lane >> 4) << 4);
    const uint32_t bRow = (uint32_t)(((lane >> 4) << 3) + (lane & 7));
    const uint32_t bKl  = (uint32_t)(((lane >> 3) & 1) << 4);

    uint32_t qh[4][4], ql[4][4];
    #pragma unroll
    for (int kk = 0; kk < 4; kk++) {
        uint32_t cofs = ((uint32_t)(kk << 5) + aKl) ^ swx;
        ldm4(qh[kk], sb + QHI + aRow * 128u + cofs);
        ldm4(ql[kk], sb + QLO + aRow * 128u + cofs);
    }

    float m_a = -1e30f, m_b = -1e30f, l_a = 0.f, l_b = 0.f;
    float oc[8][4];
    #pragma unroll
    for (int t = 0; t < 8; t++)
        #pragma unroll
        for (int r = 0; r < 4; r++) oc[t][r] = 0.f;

    const int nkb = 2 * qb + 2;
    #pragma unroll 1
    for (int kb = 0; kb < nkb; kb++) {
        CP_WAIT0();
        __syncthreads();
        const uint32_t sst = sb + STG0 + (uint32_t)(kb & 1) * 32768u;
        if (kb + 1 < nkb)
            load_kv_async(sb + STG0 + (uint32_t)((kb + 1) & 1) * 32768u,
                          kb + 1, b, bh, h, tid);
        CP_COMMIT();

        float sc[8][4];
        #pragma unroll
        for (int t = 0; t < 8; t++)
            #pragma unroll
            for (int r = 0; r < 4; r++) sc[t][r] = 0.f;
        #pragma unroll
        for (int kk = 0; kk < 4; kk++) {
            uint32_t kh[4][4], kl[4][4];
            uint32_t cofs = ((uint32_t)(kk << 5) + bKl) ^ swx;
            #pragma unroll
            for (int ng = 0; ng < 4; ng++) {
                uint32_t ro = (bRow + (uint32_t)(ng * 16)) * 128u;
                ldm4(kh[ng], sst + ro + cofs);
                ldm4(kl[ng], sst + 8192u + ro + cofs);
            }
            #pragma unroll
            for (int ng = 0; ng < 4; ng++) {
                mma_bf16(sc[2*ng],   qh[kk], &kh[ng][0]);
                mma_bf16(sc[2*ng+1], qh[kk], &kh[ng][2]);
                mma_bf16(sc[2*ng],   qh[kk], &kl[ng][0]);
                mma_bf16(sc[2*ng+1], qh[kk], &kl[ng][2]);
                mma_bf16(sc[2*ng],   ql[kk], &kh[ng][0]);
                mma_bf16(sc[2*ng+1], ql[kk], &kh[ng][2]);
            }
        }

        const int rga = qb*128 + wid*16 + (lane >> 2);
        if (kb >= 2*qb) {
            #pragma unroll
            for (int t = 0; t < 8; t++) {
                int cg = kb*64 + t*8 + ((lane & 3) << 1);
                if (cg     > rga)     sc[t][0] = -1e30f;
                if (cg + 1 > rga)     sc[t][1] = -1e30f;
                if (cg     > rga + 8) sc[t][2] = -1e30f;
                if (cg + 1 > rga + 8) sc[t][3] = -1e30f;
            }
        }

        float mxa = -1e30f, mxb = -1e30f;
        #pragma unroll
        for (int t = 0; t < 8; t++) {
            mxa = fmaxf(mxa, fmaxf(sc[t][0], sc[t][1]));
            mxb = fmaxf(mxb, fmaxf(sc[t][2], sc[t][3]));
        }
        mxa = fmaxf(mxa, __shfl_xor_sync(0xffffffffu, mxa, 1));
        mxa = fmaxf(mxa, __shfl_xor_sync(0xffffffffu, mxa, 2));
        mxb = fmaxf(mxb, __shfl_xor_sync(0xffffffffu, mxb, 1));
        mxb = fmaxf(mxb, __shfl_xor_sync(0xffffffffu, mxb, 2));
        float mna = fmaxf(m_a, mxa), mnb = fmaxf(m_b, mxb);
        float alpa = __expf(m_a - mna), alpb = __expf(m_b - mnb);
        float psa = 0.f, psb = 0.f;
        #pragma unroll
        for (int t = 0; t < 8; t++) {
            sc[t][0] = __expf(sc[t][0] - mna); psa += sc[t][0];
            sc[t][1] = __expf(sc[t][1] - mna); psa += sc[t][1];
            sc[t][2] = __expf(sc[t][2] - mnb); psb += sc[t][2];
            sc[t][3] = __expf(sc[t][3] - mnb); psb += sc[t][3];
        }
        psa += __shfl_xor_sync(0xffffffffu, psa, 1);
        psa += __shfl_xor_sync(0xffffffffu, psa, 2);
        psb += __shfl_xor_sync(0xffffffffu, psb, 1);
        psb += __shfl_xor_sync(0xffffffffu, psb, 2);
        l_a = l_a * alpa + psa;  m_a = mna;
        l_b = l_b * alpb + psb;  m_b = mnb;
        #pragma unroll
        for (int t = 0; t < 8; t++) {
            oc[t][0] *= alpa; oc[t][1] *= alpa;
            oc[t][2] *= alpb; oc[t][3] *= alpb;
        }

        #pragma unroll
        for (int kk = 0; kk < 4; kk++) {
            uint32_t ph[4], pl[4];
            splitpk(sc[2*kk][0],   sc[2*kk][1],   ph[0], pl[0]);
            splitpk(sc[2*kk][2],   sc[2*kk][3],   ph[1], pl[1]);
            splitpk(sc[2*kk+1][0], sc[2*kk+1][1], ph[2], pl[2]);
            splitpk(sc[2*kk+1][2], sc[2*kk+1][3], ph[3], pl[3]);
            uint32_t vh[4][4], vl[4][4];
            uint32_t cofs = ((uint32_t)(kk << 5) + bKl) ^ swx;
            #pragma unroll
            for (int ng = 0; ng < 4; ng++) {
                uint32_t ro = (bRow + (uint32_t)(ng * 16)) * 128u;
                ldm4(vh[ng], sst + 16384u + ro + cofs);
                ldm4(vl[ng], sst + 24576u + ro + cofs);
            }
            #pragma unroll
            for (int ng = 0; ng < 4; ng++) {
                mma_bf16(oc[2*ng],   ph, &vh[ng][0]);
                mma_bf16(oc[2*ng+1], ph, &vh[ng][2]);
                mma_bf16(oc[2*ng],   ph, &vl[ng][0]);
                mma_bf16(oc[2*ng+1], ph, &vl[ng][2]);
                mma_bf16(oc[2*ng],   pl, &vh[ng][0]);
                mma_bf16(oc[2*ng+1], pl, &vh[ng][2]);
            }
        }
    }

    float inva = 1.f / l_a, invb = 1.f / l_b;
    int ra = qb*128 + wid*16 + (lane >> 2);
    size_t baseA = (size_t)(b*S_ + ra) * D_ + h*DH_;
    size_t baseB = baseA + (size_t)8 * D_;
    #pragma unroll
    for (int t = 0; t < 8; t++) {
        int d = t*8 + ((lane & 3) << 1);
        uint32_t hi, lo;
        splitpk(oc[t][0]*inva, oc[t][1]*inva, hi, lo);
        *(uint32_t*)&g_Chi[baseA + d] = hi;
        *(uint32_t*)&g_Clo[baseA + d] = lo;
        splitpk(oc[t][2]*invb, oc[t][3]*invb, hi, lo);
        *(uint32_t*)&g_Chi[baseB + d] = hi;
        *(uint32_t*)&g_Clo[baseB + d] = lo;
    }
}

// ===========================================================================
extern "C" void kernel_launch(void* const* d_in, const int* in_sizes, int n_in,
                              void* d_out, int out_size)
{
    const float* q  = (const float*)d_in[0];
    const float* k  = (const float*)d_in[1];
    const float* v  = (const float*)d_in[2];
    const float* Wq = (const float*)d_in[3];
    const float* bq = (const float*)d_in[4];
    const float* Wk = (const float*)d_in[5];
    const float* bk = (const float*)d_in[6];
    const float* Wv = (const float*)d_in[7];
    const float* bv = (const float*)d_in[8];
    const float* Wo = (const float*)d_in[9];
    const float* bo = (const float*)d_in[10];
    float* out = (float*)d_out;

    const int gsmem = 3 * 65536;  // 196608
    cudaFuncSetAttribute(gemm_qkv_kernel, cudaFuncAttributeMaxDynamicSharedMemorySize, gsmem);
    cudaFuncSetAttribute(gemm_o_kernel,   cudaFuncAttributeMaxDynamicSharedMemorySize, gsmem);
    const int asmem = 32768 + 2 * 32768;  // 98304
    cudaFuncSetAttribute(attn_mma_kernel, cudaFuncAttributeMaxDynamicSharedMemorySize, asmem);

    const int NXB = (int)(MD_/8)/256;   // 2048
    const int NWB = (int)(DD_/8)/256;   // 512

    splitw_kernel<<<dim3(NWB, 1, 4), 256>>>(Wq, Wk, Wv, Wo);
    splitx_kernel<<<dim3(NXB, 1, 3), 256>>>(q, k, v);

    gemm_qkv_kernel<<<dim3(D_/128, MTOT/128, 3), 256, gsmem>>>(bq, bk, bv);

    vtrans_kernel<<<dim3(S_/64, B_*H_), 256>>>();

    attn_mma_kernel<<<dim3(S_/128, B_*H_), 256, asmem>>>();

    gemm_o_kernel<<<dim3(D_/128, MTOT/128), 256, gsmem>>>(bo, out);
}